// round 1
// baseline (speedup 1.0000x reference)
#include <cuda_runtime.h>

// ---------------------------------------------------------------------------
// Problem constants: a [B=16, C=64, H=256, W=256] fp32
//   q,k,v = 1x1 conv (channel mix, [64x64] weights + bias)
//   per (b,c): S = Q K^T / 16 ; P = softmax_rows(S) ; O = P V
//   out = a + W_adapt * O
// ---------------------------------------------------------------------------

#define N_ELEM (16 * 64 * 256 * 256)   // 67,108,864 floats per tensor

// Scratch for q, k, v (alloc-free rule: __device__ globals)
__device__ float g_q[N_ELEM];
__device__ float g_k[N_ELEM];
__device__ float g_v[N_ELEM];

// ---------------------------------------------------------------------------
// Kernel A: QKV 1x1 convs.
// grid = 16 batches * 256 position-blocks, block = 256 threads.
// Each thread handles one spatial position p (=h*256+w): caches a[:,p] (64
// regs), computes q/k/v[o] for o=0..63 with weights in smem (float4 LDS
// broadcast -> 1 LDS.128 : 4 FFMA issue ratio per operand stream).
// ---------------------------------------------------------------------------
#define QKV_SMEM_FLOATS (3 * 4096 + 3 * 64)
#define QKV_SMEM_BYTES  (QKV_SMEM_FLOATS * 4)

__global__ __launch_bounds__(256) void qkv_kernel(
    const float* __restrict__ a,
    const float* __restrict__ Wq, const float* __restrict__ bq,
    const float* __restrict__ Wk, const float* __restrict__ bk,
    const float* __restrict__ Wv, const float* __restrict__ bv)
{
    extern __shared__ float sm[];
    float* sWq = sm;
    float* sWk = sm + 4096;
    float* sWv = sm + 8192;
    float* sbq = sm + 12288;
    float* sbk = sm + 12352;
    float* sbv = sm + 12416;

    const int tid = threadIdx.x;
    for (int i = tid; i < 4096; i += 256) {
        sWq[i] = Wq[i];
        sWk[i] = Wk[i];
        sWv[i] = Wv[i];
    }
    if (tid < 64) {
        sbq[tid] = bq[tid];
        sbk[tid] = bk[tid];
        sbv[tid] = bv[tid];
    }
    __syncthreads();

    const int b = blockIdx.x >> 8;                 // 0..15
    const int p = ((blockIdx.x & 255) << 8) + tid; // 0..65535 within batch
    const size_t boff = (size_t)b * 64 * 65536 + (size_t)p;

    // cache the input channel column
    float areg[64];
    #pragma unroll
    for (int c = 0; c < 64; c++) areg[c] = a[boff + (size_t)c * 65536];

    float* qo = g_q + boff;
    float* ko = g_k + boff;
    float* vo = g_v + boff;

    #pragma unroll 2
    for (int o = 0; o < 64; o++) {
        float aq = sbq[o];
        float ak = sbk[o];
        float av = sbv[o];
        const float4* wq4 = (const float4*)(sWq + o * 64);
        const float4* wk4 = (const float4*)(sWk + o * 64);
        const float4* wv4 = (const float4*)(sWv + o * 64);
        #pragma unroll
        for (int j = 0; j < 16; j++) {
            const float4 q4 = wq4[j];
            const float4 k4 = wk4[j];
            const float4 v4 = wv4[j];
            const float a0 = areg[4 * j + 0];
            const float a1 = areg[4 * j + 1];
            const float a2 = areg[4 * j + 2];
            const float a3 = areg[4 * j + 3];
            aq += q4.x * a0 + q4.y * a1 + q4.z * a2 + q4.w * a3;
            ak += k4.x * a0 + k4.y * a1 + k4.z * a2 + k4.w * a3;
            av += v4.x * a0 + v4.y * a1 + v4.z * a2 + v4.w * a3;
        }
        qo[(size_t)o * 65536] = aq;
        ko[(size_t)o * 65536] = ak;
        vo[(size_t)o * 65536] = av;
    }
}

// ---------------------------------------------------------------------------
// Kernel B: fused attention per (b,c) slice.
// grid = (4 q-chunks, 1024 bc), block = 256 threads.
// smem: Q tile [64][256], K/V tile [64][260] (pad 4), S tile [64][260],
//       1/rowsum [64]. Total 198,912 B dynamic smem.
// S phase: 4x4 micro-tile per thread with interleaved rows (i, i+16, i+32,
// i+48) so the 16 distinct K-row LDS.128 addresses in a warp land on >=8
// banks (2-way worst case, at the 128B/cyc crossbar floor anyway).
// Softmax: part-strided columns (bank = 4*row+part mod 32 -> conflict-free);
// exp values stay unnormalized in smem, 1/rowsum applied in the epilogue.
// PV phase: 4 rows x 16 cols per thread (64 fp32 accumulators).
// ---------------------------------------------------------------------------
#define ATTN_SMEM_FLOATS (16384 + 16640 + 16640 + 64)
#define ATTN_SMEM_BYTES  (ATTN_SMEM_FLOATS * 4)

__global__ __launch_bounds__(256) void attn_kernel(
    const float* __restrict__ a,
    const float* __restrict__ Wad,
    float* __restrict__ out)
{
    extern __shared__ float sm[];
    float* sQ   = sm;             // [64][256]
    float* sK   = sm + 16384;     // [64][260]
    float* sS   = sm + 33024;     // [64][260]
    float* sInv = sm + 49664;     // [64]

    const int tid = threadIdx.x;
    const int bc = blockIdx.y;    // 0..1023
    const int qc = blockIdx.x;    // 0..3
    const size_t base = (size_t)bc * 65536;

    const float* Qg = g_q + base + (size_t)qc * 16384;
    const float* Kg = g_k + base;
    const float* Vg = g_v + base;

    // ---- load Q tile (flat float4 copy) ----
    {
        const float4* src = (const float4*)Qg;
        float4* dst = (float4*)sQ;
        for (int i = tid; i < 4096; i += 256) dst[i] = src[i];
    }

    const int ti = tid >> 4;   // 0..15
    const int tj = tid & 15;   // 0..15

    // ---- S = Q K^T * (1/16) ----
    for (int kt = 0; kt < 4; kt++) {
        __syncthreads();
        {
            const float4* src = (const float4*)(Kg + kt * 16384);
            for (int i = tid; i < 4096; i += 256) {
                const int r = i >> 6, c = i & 63;
                ((float4*)(sK + r * 260))[c] = src[i];
            }
        }
        __syncthreads();

        float acc[4][4];
        #pragma unroll
        for (int ii = 0; ii < 4; ii++)
            #pragma unroll
            for (int jj = 0; jj < 4; jj++) acc[ii][jj] = 0.f;

        #pragma unroll 4
        for (int w = 0; w < 256; w += 4) {
            float4 qv[4], kv[4];
            #pragma unroll
            for (int ii = 0; ii < 4; ii++)
                qv[ii] = *(const float4*)(sQ + (ti + 16 * ii) * 256 + w);
            #pragma unroll
            for (int jj = 0; jj < 4; jj++)
                kv[jj] = *(const float4*)(sK + (tj + 16 * jj) * 260 + w);
            #pragma unroll
            for (int ii = 0; ii < 4; ii++)
                #pragma unroll
                for (int jj = 0; jj < 4; jj++) {
                    acc[ii][jj] += qv[ii].x * kv[jj].x;
                    acc[ii][jj] += qv[ii].y * kv[jj].y;
                    acc[ii][jj] += qv[ii].z * kv[jj].z;
                    acc[ii][jj] += qv[ii].w * kv[jj].w;
                }
        }

        #pragma unroll
        for (int ii = 0; ii < 4; ii++)
            #pragma unroll
            for (int jj = 0; jj < 4; jj++)
                sS[(ti + 16 * ii) * 260 + kt * 64 + tj + 16 * jj] =
                    acc[ii][jj] * 0.0625f;
    }
    __syncthreads();

    // ---- softmax over each S row (unnormalized exp kept in sS) ----
    {
        const int row = tid >> 2;    // 0..63
        const int part = tid & 3;    // 0..3
        float* srow = sS + row * 260 + part;
        float mx = -1e30f;
        #pragma unroll 8
        for (int j = 0; j < 64; j++) mx = fmaxf(mx, srow[4 * j]);
        mx = fmaxf(mx, __shfl_xor_sync(0xffffffffu, mx, 1));
        mx = fmaxf(mx, __shfl_xor_sync(0xffffffffu, mx, 2));
        float ssum = 0.f;
        #pragma unroll 8
        for (int j = 0; j < 64; j++) {
            const float e = __expf(srow[4 * j] - mx);
            srow[4 * j] = e;
            ssum += e;
        }
        ssum += __shfl_xor_sync(0xffffffffu, ssum, 1);
        ssum += __shfl_xor_sync(0xffffffffu, ssum, 2);
        if (part == 0) sInv[row] = 1.0f / ssum;
    }

    // ---- O = P V (accumulate unnormalized; normalize in epilogue) ----
    float4 accO[4][4];
    #pragma unroll
    for (int ii = 0; ii < 4; ii++)
        #pragma unroll
        for (int cc = 0; cc < 4; cc++)
            accO[ii][cc] = make_float4(0.f, 0.f, 0.f, 0.f);

    for (int vt = 0; vt < 4; vt++) {
        __syncthreads();
        {
            const float4* src = (const float4*)(Vg + vt * 16384);
            for (int i = tid; i < 4096; i += 256) {
                const int r = i >> 6, c = i & 63;
                ((float4*)(sK + r * 260))[c] = src[i];
            }
        }
        __syncthreads();

        #pragma unroll 2
        for (int g = 0; g < 64; g++) {
            float p[4];
            #pragma unroll
            for (int ii = 0; ii < 4; ii++)
                p[ii] = sS[(ti + 16 * ii) * 260 + vt * 64 + g];
            float4 v4[4];
            #pragma unroll
            for (int cc = 0; cc < 4; cc++)
                v4[cc] = *(const float4*)(sK + g * 260 + tj * 16 + cc * 4);
            #pragma unroll
            for (int ii = 0; ii < 4; ii++)
                #pragma unroll
                for (int cc = 0; cc < 4; cc++) {
                    accO[ii][cc].x += p[ii] * v4[cc].x;
                    accO[ii][cc].y += p[ii] * v4[cc].y;
                    accO[ii][cc].z += p[ii] * v4[cc].z;
                    accO[ii][cc].w += p[ii] * v4[cc].w;
                }
        }
    }

    // ---- epilogue: out = a + W_adapt * O / rowsum ----
    const float wad = Wad[0];
    #pragma unroll
    for (int ii = 0; ii < 4; ii++) {
        const int r = ti + 16 * ii;
        const float s = wad * sInv[r];
        const size_t rowoff = base + (size_t)(qc * 64 + r) * 256 + tj * 16;
        #pragma unroll
        for (int cc = 0; cc < 4; cc++) {
            const float4 av = *(const float4*)(a + rowoff + cc * 4);
            float4 o;
            o.x = av.x + s * accO[ii][cc].x;
            o.y = av.y + s * accO[ii][cc].y;
            o.z = av.z + s * accO[ii][cc].z;
            o.w = av.w + s * accO[ii][cc].w;
            *(float4*)(out + rowoff + cc * 4) = o;
        }
    }
}

// ---------------------------------------------------------------------------
extern "C" void kernel_launch(void* const* d_in, const int* in_sizes, int n_in,
                              void* d_out, int out_size)
{
    const float* a    = (const float*)d_in[0];
    const float* Wq   = (const float*)d_in[1];
    const float* bq   = (const float*)d_in[2];
    const float* Wk   = (const float*)d_in[3];
    const float* bk   = (const float*)d_in[4];
    const float* Wv   = (const float*)d_in[5];
    const float* bv   = (const float*)d_in[6];
    const float* Wad  = (const float*)d_in[7];
    float* out = (float*)d_out;

    cudaFuncSetAttribute(qkv_kernel,
                         cudaFuncAttributeMaxDynamicSharedMemorySize,
                         QKV_SMEM_BYTES);
    cudaFuncSetAttribute(attn_kernel,
                         cudaFuncAttributeMaxDynamicSharedMemorySize,
                         ATTN_SMEM_BYTES);

    qkv_kernel<<<16 * 256, 256, QKV_SMEM_BYTES>>>(a, Wq, bq, Wk, bk, Wv, bv);
    attn_kernel<<<dim3(4, 1024), 256, ATTN_SMEM_BYTES>>>(a, Wad, out);
}

// round 3
// speedup vs baseline: 5.5919x; 5.5919x over previous
#include <cuda_runtime.h>
#include <cuda_fp16.h>
#include <cstdint>

// ---------------------------------------------------------------------------
// a [B=16, C=64, H=256, W=256] fp32
//   q,k,v = 1x1 conv;  per (b,c): S=QK^T/16, P=softmax(S), O=PV
//   out = a + W_adapt * O
// Round 3: classic mma.sync (HMMA) fp16 everywhere — tcgen05 is unavailable
// on this build's plain sm_103 PTX target.
// ---------------------------------------------------------------------------

#define N_ELEM (16 * 64 * 256 * 256)

__device__ __half g_q[N_ELEM];   // [b*64+o][h*256+w]
__device__ __half g_k[N_ELEM];
__device__ __half g_v[N_ELEM];

// ============================ helpers ======================================

__device__ __forceinline__ uint32_t su32(const void* p) {
    return (uint32_t)__cvta_generic_to_shared(p);
}

__device__ __forceinline__ void ldsm4(uint32_t* r, uint32_t addr) {
    asm volatile("ldmatrix.sync.aligned.m8n8.x4.shared.b16 {%0,%1,%2,%3}, [%4];"
        : "=r"(r[0]), "=r"(r[1]), "=r"(r[2]), "=r"(r[3]) : "r"(addr));
}
__device__ __forceinline__ void ldsm4t(uint32_t* r, uint32_t addr) {
    asm volatile("ldmatrix.sync.aligned.m8n8.x4.trans.shared.b16 {%0,%1,%2,%3}, [%4];"
        : "=r"(r[0]), "=r"(r[1]), "=r"(r[2]), "=r"(r[3]) : "r"(addr));
}
__device__ __forceinline__ void mma16816(float* d, const uint32_t* a, const uint32_t* b) {
    asm volatile("mma.sync.aligned.m16n8k16.row.col.f32.f16.f16.f32 "
        "{%0,%1,%2,%3}, {%4,%5,%6,%7}, {%8,%9}, {%0,%1,%2,%3};"
        : "+f"(d[0]), "+f"(d[1]), "+f"(d[2]), "+f"(d[3])
        : "r"(a[0]), "r"(a[1]), "r"(a[2]), "r"(a[3]), "r"(b[0]), "r"(b[1]));
}
__device__ __forceinline__ float ex2f(float x) {
    float y; asm("ex2.approx.f32 %0, %1;" : "=f"(y) : "f"(x)); return y;
}
__device__ __forceinline__ uint32_t packh2(float lo, float hi) {
    __half2 h = __floats2half2_rn(lo, hi);
    return *(uint32_t*)&h;
}

// ======================= Kernel A: QKV (HMMA GEMM) =========================
// grid = 16 * 256 (256-position tiles), block = 256 (8 warps x 32 rows).
// smem: sA 256x64 fp16 (128B rows, XOR-swizzled 16B units) @0;
//       sW 3 x 64x64 fp16 @32768; bias fp32 @57344.
#define QKV_SMEM_BYTES (32768 + 24576 + 768)

__global__ __launch_bounds__(256) void qkv_kernel(
    const float* __restrict__ a,
    const float* __restrict__ Wq, const float* __restrict__ bq,
    const float* __restrict__ Wk, const float* __restrict__ bk,
    const float* __restrict__ Wv, const float* __restrict__ bv)
{
    extern __shared__ char sm[];
    char* sA = sm;
    char* sW = sm + 32768;
    float* sB = (float*)(sm + 57344);

    const int tid = threadIdx.x;
    const int b = blockIdx.x >> 8;
    const int P0 = (blockIdx.x & 255) << 8;

    // weights -> fp16 smem (rows o, 8x16B units, swizzled)
    for (int i = tid; i < 6144; i += 256) {
        const int m = i >> 11, j = i & 2047;
        const int o = j >> 5, c2 = j & 31;
        const float* W = (m == 0) ? Wq : ((m == 1) ? Wk : Wv);
        const float f0 = W[o * 64 + 2 * c2];
        const float f1 = W[o * 64 + 2 * c2 + 1];
        const int u = c2 >> 2;
        *(uint32_t*)(sW + m * 8192 + o * 128 + ((u ^ (o & 7)) << 4) + (c2 & 3) * 4)
            = packh2(f0, f1);
    }
    if (tid < 192) {
        const float* bb = (tid < 64) ? bq : ((tid < 128) ? bk : bv);
        sB[tid] = bb[tid & 63];
    }

    // a tile: thread tid owns position p = P0 + tid, loops channels
    {
        const size_t basep = (size_t)b * 64 * 65536 + (size_t)P0 + tid;
        #pragma unroll
        for (int c2 = 0; c2 < 32; c2++) {
            const float f0 = a[basep + (size_t)(2 * c2) * 65536];
            const float f1 = a[basep + (size_t)(2 * c2 + 1) * 65536];
            const int u = c2 >> 2;
            *(uint32_t*)(sA + tid * 128 + ((u ^ (tid & 7)) << 4) + (c2 & 3) * 4)
                = packh2(f0, f1);
        }
    }
    __syncthreads();

    const int wid = tid >> 5, lane = tid & 31;
    const int R0 = wid * 32;
    const int sel = lane >> 3, wl = lane & 7;
    const uint32_t sAb = su32(sA), sWb = su32(sW);

    for (int mat = 0; mat < 3; mat++) {
        float c[2][8][4];
        #pragma unroll
        for (int m = 0; m < 2; m++)
            #pragma unroll
            for (int n = 0; n < 8; n++)
                #pragma unroll
                for (int q = 0; q < 4; q++) c[m][n][q] = 0.f;

        #pragma unroll
        for (int ks = 0; ks < 4; ks++) {
            uint32_t a0[4], a1[4];
            {
                int r = R0 + wl + ((sel & 1) << 3);
                const int u = 2 * ks + (sel >> 1);
                ldsm4(a0, sAb + r * 128 + ((u ^ (r & 7)) << 4));
                r += 16;
                ldsm4(a1, sAb + r * 128 + ((u ^ (r & 7)) << 4));
            }
            #pragma unroll
            for (int ntp = 0; ntp < 4; ntp++) {
                uint32_t bb[4];
                const int rB = ntp * 16 + wl + ((sel >> 1) << 3);
                const int uB = 2 * ks + (sel & 1);
                ldsm4(bb, sWb + mat * 8192 + rB * 128 + ((uB ^ (rB & 7)) << 4));
                mma16816(c[0][2 * ntp],     a0, bb);
                mma16816(c[0][2 * ntp + 1], a0, bb + 2);
                mma16816(c[1][2 * ntp],     a1, bb);
                mma16816(c[1][2 * ntp + 1], a1, bb + 2);
            }
        }

        __half* g = (mat == 0) ? g_q : ((mat == 1) ? g_k : g_v);
        const int lr = lane >> 2, lc = lane & 3;
        #pragma unroll
        for (int m = 0; m < 2; m++) {
            #pragma unroll
            for (int nt = 0; nt < 8; nt++) {
                const int o = nt * 8 + 2 * lc;
                const int p = P0 + R0 + m * 16 + lr;
                const float bo0 = sB[mat * 64 + o];
                const float bo1 = sB[mat * 64 + o + 1];
                const size_t i00 = (size_t)(b * 64 + o) * 65536 + p;
                g[i00]             = __float2half_rn(c[m][nt][0] + bo0);
                g[i00 + 65536]     = __float2half_rn(c[m][nt][1] + bo1);
                g[i00 + 8]         = __float2half_rn(c[m][nt][2] + bo0);
                g[i00 + 65536 + 8] = __float2half_rn(c[m][nt][3] + bo1);
            }
        }
    }
}

// ======================= Kernel B: HMMA attention ==========================
// grid = 2048 (bc, 128-row half), block = 256 (8 warps x 16 rows).
// smem: sQ 128x256 fp16 @0 (64KB), sK/sV 256x256 fp16 @65536 (128KB).
// Rows are 512B = 32 x 16B units, unit index XOR-swizzled with (row&7):
// every ldmatrix phase and every fill is shared-bank conflict-free.
#define ATTN_SMEM_BYTES (65536 + 131072)

__global__ __launch_bounds__(256) void attn_kernel(
    const float* __restrict__ a,
    const float* __restrict__ Wad,
    float* __restrict__ out)
{
    extern __shared__ char sm[];
    char* sQ  = sm;
    char* sKV = sm + 65536;
    const int tid = threadIdx.x, wid = tid >> 5, lane = tid & 31;
    const int bc = blockIdx.x >> 1, half = blockIdx.x & 1;
    const size_t base = (size_t)bc * 65536;

    // fill Q tile (128 rows x 32 units)
    {
        const uint4* src = (const uint4*)(g_q + base + (size_t)half * 32768);
        for (int i = tid; i < 4096; i += 256) {
            const int r = i >> 5, u = i & 31;
            *(uint4*)(sQ + r * 512 + ((u ^ (r & 7)) << 4)) = src[i];
        }
    }
    // fill K tile (256 rows x 32 units)
    {
        const uint4* src = (const uint4*)(g_k + base);
        for (int i = tid; i < 8192; i += 256) {
            const int r = i >> 5, u = i & 31;
            *(uint4*)(sKV + r * 512 + ((u ^ (r & 7)) << 4)) = src[i];
        }
    }
    __syncthreads();

    const int R0 = wid * 16;
    const int sel = lane >> 3, wl = lane & 7;
    const uint32_t sQb = su32(sQ), sKVb = su32(sKV);

    // ---- S = Q K^T : C fragments c[j] cover g-cols 8j..8j+7 ----
    float c[32][4];
    #pragma unroll
    for (int j = 0; j < 32; j++)
        #pragma unroll
        for (int q = 0; q < 4; q++) c[j][q] = 0.f;

    for (int ks = 0; ks < 16; ks++) {
        uint32_t av[4];
        {
            const int r = R0 + wl + ((sel & 1) << 3);
            const int u = 2 * ks + (sel >> 1);
            ldsm4(av, sQb + r * 512 + ((u ^ (r & 7)) << 4));
        }
        #pragma unroll
        for (int ntp = 0; ntp < 16; ntp++) {
            uint32_t bb[4];
            const int rB = ntp * 16 + wl + ((sel >> 1) << 3);
            const int uB = 2 * ks + (sel & 1);
            ldsm4(bb, sKVb + rB * 512 + ((uB ^ (rB & 7)) << 4));
            mma16816(c[2 * ntp],     av, bb);
            mma16816(c[2 * ntp + 1], av, bb + 2);
        }
    }
    __syncthreads();   // every warp finished reading sK

    // fill V tile into the same buffer (overlaps with softmax below)
    {
        const uint4* src = (const uint4*)(g_v + base);
        for (int i = tid; i < 8192; i += 256) {
            const int r = i >> 5, u = i & 31;
            *(uint4*)(sKV + r * 512 + ((u ^ (r & 7)) << 4)) = src[i];
        }
    }

    // ---- softmax, all in registers (rows r=lane/4 and r+8) ----
    float mx0 = -3.0e38f, mx1 = -3.0e38f;
    #pragma unroll
    for (int j = 0; j < 32; j++) {
        mx0 = fmaxf(mx0, fmaxf(c[j][0], c[j][1]));
        mx1 = fmaxf(mx1, fmaxf(c[j][2], c[j][3]));
    }
    mx0 = fmaxf(mx0, __shfl_xor_sync(0xffffffffu, mx0, 1));
    mx0 = fmaxf(mx0, __shfl_xor_sync(0xffffffffu, mx0, 2));
    mx1 = fmaxf(mx1, __shfl_xor_sync(0xffffffffu, mx1, 1));
    mx1 = fmaxf(mx1, __shfl_xor_sync(0xffffffffu, mx1, 2));

    const float KS = 1.4426950408889634f / 16.f;  // log2(e) * scale(1/16)
    float s0 = 0.f, s1 = 0.f;
    uint32_t pa[16][4];   // P re-packed as A fragments (FA2 layout identity)
    #pragma unroll
    for (int j = 0; j < 16; j++) {
        const float e00 = ex2f((c[2*j][0]   - mx0) * KS);
        const float e01 = ex2f((c[2*j][1]   - mx0) * KS);
        const float e02 = ex2f((c[2*j][2]   - mx1) * KS);
        const float e03 = ex2f((c[2*j][3]   - mx1) * KS);
        const float e10 = ex2f((c[2*j+1][0] - mx0) * KS);
        const float e11 = ex2f((c[2*j+1][1] - mx0) * KS);
        const float e12 = ex2f((c[2*j+1][2] - mx1) * KS);
        const float e13 = ex2f((c[2*j+1][3] - mx1) * KS);
        s0 += e00 + e01 + e10 + e11;
        s1 += e02 + e03 + e12 + e13;
        pa[j][0] = packh2(e00, e01);
        pa[j][1] = packh2(e02, e03);
        pa[j][2] = packh2(e10, e11);
        pa[j][3] = packh2(e12, e13);
    }
    s0 += __shfl_xor_sync(0xffffffffu, s0, 1);
    s0 += __shfl_xor_sync(0xffffffffu, s0, 2);
    s1 += __shfl_xor_sync(0xffffffffu, s1, 1);
    s1 += __shfl_xor_sync(0xffffffffu, s1, 2);

    __syncthreads();   // sV ready

    // ---- O = P V ; epilogue fused (residual + W_adapt/rowsum) ----
    const float wad = Wad[0];
    const float f0 = wad / s0, f1 = wad / s1;
    const int lr = lane >> 2, lc = lane & 3;
    const int h0 = half * 128 + R0 + lr;

    for (int wh = 0; wh < 2; wh++) {
        float o[16][4];
        #pragma unroll
        for (int n = 0; n < 16; n++)
            #pragma unroll
            for (int q = 0; q < 4; q++) o[n][q] = 0.f;

        #pragma unroll
        for (int ks = 0; ks < 16; ks++) {
            #pragma unroll
            for (int ntp = 0; ntp < 8; ntp++) {
                uint32_t bb[4];
                const int rV = 16 * ks + wl + ((sel & 1) << 3);
                const int uV = wh * 16 + 2 * ntp + (sel >> 1);
                ldsm4t(bb, sKVb + rV * 512 + ((uV ^ (rV & 7)) << 4));
                mma16816(o[2 * ntp],     pa[ks], bb);
                mma16816(o[2 * ntp + 1], pa[ks], bb + 2);
            }
        }

        #pragma unroll
        for (int nt = 0; nt < 16; nt++) {
            const int col = wh * 128 + nt * 8 + 2 * lc;
            const size_t i0 = base + (size_t)h0 * 256 + col;
            const float2 av0 = *(const float2*)(a + i0);
            float2 r0v;
            r0v.x = av0.x + f0 * o[nt][0];
            r0v.y = av0.y + f0 * o[nt][1];
            *(float2*)(out + i0) = r0v;
            const size_t i1 = i0 + 8 * 256;
            const float2 av1 = *(const float2*)(a + i1);
            float2 r1v;
            r1v.x = av1.x + f1 * o[nt][2];
            r1v.y = av1.y + f1 * o[nt][3];
            *(float2*)(out + i1) = r1v;
        }
    }
}

// ---------------------------------------------------------------------------
extern "C" void kernel_launch(void* const* d_in, const int* in_sizes, int n_in,
                              void* d_out, int out_size)
{
    const float* a   = (const float*)d_in[0];
    const float* Wq  = (const float*)d_in[1];
    const float* bq  = (const float*)d_in[2];
    const float* Wk  = (const float*)d_in[3];
    const float* bk  = (const float*)d_in[4];
    const float* Wv  = (const float*)d_in[5];
    const float* bv  = (const float*)d_in[6];
    const float* Wad = (const float*)d_in[7];
    float* out = (float*)d_out;

    cudaFuncSetAttribute(qkv_kernel,
                         cudaFuncAttributeMaxDynamicSharedMemorySize, QKV_SMEM_BYTES);
    cudaFuncSetAttribute(attn_kernel,
                         cudaFuncAttributeMaxDynamicSharedMemorySize, ATTN_SMEM_BYTES);

    qkv_kernel<<<16 * 256, 256, QKV_SMEM_BYTES>>>(a, Wq, bq, Wk, bk, Wv, bv);
    attn_kernel<<<2048, 256, ATTN_SMEM_BYTES>>>(a, Wad, out);
}

// round 6
// speedup vs baseline: 5.6597x; 1.0121x over previous
#include <cuda_runtime.h>
#include <cuda_fp16.h>
#include <cstdint>

// ---------------------------------------------------------------------------
// a [B=16, C=64, H=256, W=256] fp32
//   q,k,v = 1x1 conv;  per (b,c): S=QK^T/16, P=softmax(S), O=PV
//   out = a + W_adapt * O
// Round 6 (third attempt of the R4 design; two broker-side container
// failures gave no kernel signal): 16-warp n-split HMMA attention;
// transposed QKV GEMM with staged coalesced stores.
// ---------------------------------------------------------------------------

#define N_ELEM (16 * 64 * 256 * 256)

__device__ __half g_q[N_ELEM];   // [b*64+o][h*256+w]
__device__ __half g_k[N_ELEM];
__device__ __half g_v[N_ELEM];

// ============================ helpers ======================================

__device__ __forceinline__ uint32_t su32(const void* p) {
    return (uint32_t)__cvta_generic_to_shared(p);
}
__device__ __forceinline__ void ldsm4(uint32_t* r, uint32_t addr) {
    asm volatile("ldmatrix.sync.aligned.m8n8.x4.shared.b16 {%0,%1,%2,%3}, [%4];"
        : "=r"(r[0]), "=r"(r[1]), "=r"(r[2]), "=r"(r[3]) : "r"(addr));
}
__device__ __forceinline__ void ldsm4t(uint32_t* r, uint32_t addr) {
    asm volatile("ldmatrix.sync.aligned.m8n8.x4.trans.shared.b16 {%0,%1,%2,%3}, [%4];"
        : "=r"(r[0]), "=r"(r[1]), "=r"(r[2]), "=r"(r[3]) : "r"(addr));
}
__device__ __forceinline__ void mma16816(float* d, const uint32_t* a, const uint32_t* b) {
    asm volatile("mma.sync.aligned.m16n8k16.row.col.f32.f16.f16.f32 "
        "{%0,%1,%2,%3}, {%4,%5,%6,%7}, {%8,%9}, {%0,%1,%2,%3};"
        : "+f"(d[0]), "+f"(d[1]), "+f"(d[2]), "+f"(d[3])
        : "r"(a[0]), "r"(a[1]), "r"(a[2]), "r"(a[3]), "r"(b[0]), "r"(b[1]));
}
__device__ __forceinline__ float ex2f(float x) {
    float y; asm("ex2.approx.f32 %0, %1;" : "=f"(y) : "f"(x)); return y;
}
__device__ __forceinline__ uint32_t packh2(float lo, float hi) {
    __half2 h = __floats2half2_rn(lo, hi);
    return *(uint32_t*)&h;
}

// ======================= Kernel A: QKV (HMMA, C = W * a^T) =================
// grid = 16*256 (256-position tiles), block = 256 (8 warps; warp owns a
// 32-position N-chunk, all 64 output channels).
// smem: sA [p][c] fp16 128B-row swizzled @0 (32KB); sW [o][c] x3 @32768
// (24KB); bias @57344; stage [o][p] fp16 512B-row unit-swizzled @58112 (32KB).
#define QKV_STG_OFF 58112
#define QKV_SMEM_BYTES (58112 + 32768)

__global__ __launch_bounds__(256, 2) void qkv_kernel(
    const float* __restrict__ a,
    const float* __restrict__ Wq, const float* __restrict__ bq,
    const float* __restrict__ Wk, const float* __restrict__ bk,
    const float* __restrict__ Wv, const float* __restrict__ bv)
{
    extern __shared__ char sm[];
    char* sA = sm;
    char* sW = sm + 32768;
    float* sB = (float*)(sm + 57344);
    char* sStage = sm + QKV_STG_OFF;

    const int tid = threadIdx.x;
    const int b = blockIdx.x >> 8;
    const int P0 = (blockIdx.x & 255) << 8;

    // weights -> fp16 smem rows o (swizzled 16B units)
    for (int i = tid; i < 6144; i += 256) {
        const int m = i >> 11, j = i & 2047;
        const int o = j >> 5, c2 = j & 31;
        const float* W = (m == 0) ? Wq : ((m == 1) ? Wk : Wv);
        const float f0 = W[o * 64 + 2 * c2];
        const float f1 = W[o * 64 + 2 * c2 + 1];
        const int u = c2 >> 2;
        *(uint32_t*)(sW + m * 8192 + o * 128 + ((u ^ (o & 7)) << 4) + (c2 & 3) * 4)
            = packh2(f0, f1);
    }
    if (tid < 192) {
        const float* bb = (tid < 64) ? bq : ((tid < 128) ? bk : bv);
        sB[tid] = bb[tid & 63];
    }
    // a tile rows p (swizzled)
    {
        const size_t basep = (size_t)b * 64 * 65536 + (size_t)P0 + tid;
        #pragma unroll
        for (int c2 = 0; c2 < 32; c2++) {
            const float f0 = a[basep + (size_t)(2 * c2) * 65536];
            const float f1 = a[basep + (size_t)(2 * c2 + 1) * 65536];
            const int u = c2 >> 2;
            *(uint32_t*)(sA + tid * 128 + ((u ^ (tid & 7)) << 4) + (c2 & 3) * 4)
                = packh2(f0, f1);
        }
    }
    __syncthreads();

    const int wid = tid >> 5, lane = tid & 31;
    const int wp0 = wid * 32;                 // warp's position chunk
    const int sel = lane >> 3, wl = lane & 7;
    const int lr = lane >> 2, lc = lane & 3;
    const uint32_t sAb = su32(sA), sWb = su32(sW);

    for (int mat = 0; mat < 3; mat++) {
        float c[4][4][4];
        #pragma unroll
        for (int mt = 0; mt < 4; mt++)
            #pragma unroll
            for (int n = 0; n < 4; n++)
                #pragma unroll
                for (int q = 0; q < 4; q++) c[mt][n][q] = 0.f;

        #pragma unroll
        for (int ng = 0; ng < 2; ng++) {
            uint32_t bfr[4][4];
            #pragma unroll
            for (int ks = 0; ks < 4; ks++) {
                const int rB = wp0 + ng * 16 + wl + ((sel >> 1) << 3);
                const int uB = 2 * ks + (sel & 1);
                ldsm4(bfr[ks], sAb + rB * 128 + ((uB ^ (rB & 7)) << 4));
            }
            #pragma unroll
            for (int mt = 0; mt < 4; mt++) {
                #pragma unroll
                for (int ks = 0; ks < 4; ks++) {
                    uint32_t afr[4];
                    const int rA = mt * 16 + wl + ((sel & 1) << 3);
                    const int uA = 2 * ks + (sel >> 1);
                    ldsm4(afr, sWb + mat * 8192 + rA * 128 + ((uA ^ (rA & 7)) << 4));
                    mma16816(c[mt][2 * ng],     afr, bfr[ks]);
                    mma16816(c[mt][2 * ng + 1], afr, bfr[ks] + 2);
                }
            }
        }

        // bias + pack + stage ([o][p], unit-swizzled)
        #pragma unroll
        for (int mt = 0; mt < 4; mt++) {
            const int o0 = mt * 16 + lr, o1 = o0 + 8;
            const float b0 = sB[mat * 64 + o0];
            const float b1 = sB[mat * 64 + o1];
            #pragma unroll
            for (int j = 0; j < 4; j++) {
                const int colp = wp0 + j * 8 + 2 * lc;
                const int pu = colp >> 3, pb = (colp & 7) * 2;
                *(uint32_t*)(sStage + o0 * 512 + ((pu ^ (o0 & 7)) << 4) + pb)
                    = packh2(c[mt][j][0] + b0, c[mt][j][1] + b0);
                *(uint32_t*)(sStage + o1 * 512 + ((pu ^ (o1 & 7)) << 4) + pb)
                    = packh2(c[mt][j][2] + b1, c[mt][j][3] + b1);
            }
        }
        __syncthreads();

        // readout: warp owns 8 channels; lane = 16B unit -> 512B/channel STG
        __half* g = (mat == 0) ? g_q : ((mat == 1) ? g_k : g_v);
        #pragma unroll
        for (int oo = 0; oo < 8; oo++) {
            const int o = wid * 8 + oo;
            const uint4 val = *(const uint4*)(sStage + o * 512 + ((lane ^ (o & 7)) << 4));
            *(uint4*)(g + (size_t)(b * 64 + o) * 65536 + P0 + lane * 8) = val;
        }
        __syncthreads();
    }
}

// ======================= Kernel B: HMMA attention (16 warps) ===============
// grid = 2048 (bc, 128-row half), block = 512.
// warp w: rows R0=(w&7)*16, col-half nh=w>>3.
// smem: sQ @0 (64KB), sKV @66560 (128KB), sSum @197632 (1KB);
//       exchange region EX @0 (66,560B, reuses dead Q; never overlaps KV).
#define A_OFF_KV   66560
#define A_OFF_SUM  197632
#define ATTN_SMEM_BYTES 198656

__global__ __launch_bounds__(512) void attn_kernel(
    const float* __restrict__ a,
    const float* __restrict__ Wad,
    float* __restrict__ out)
{
    extern __shared__ char sm[];
    char* sQ  = sm;
    char* sKV = sm + A_OFF_KV;
    float* sSum = (float*)(sm + A_OFF_SUM);
    float* sEX = (float*)sm;                   // stride 130 floats per row

    const int tid = threadIdx.x, wid = tid >> 5, lane = tid & 31;
    const int nh = wid >> 3;                   // col half
    const int R0 = (wid & 7) * 16;             // row base
    const int bc = blockIdx.x >> 1, half = blockIdx.x & 1;
    const size_t base = (size_t)bc * 65536;

    // fill Q (128 rows) and K (256 rows)
    {
        const uint4* src = (const uint4*)(g_q + base + (size_t)half * 32768);
        for (int i = tid; i < 4096; i += 512) {
            const int r = i >> 5, u = i & 31;
            *(uint4*)(sQ + r * 512 + ((u ^ (r & 7)) << 4)) = src[i];
        }
    }
    {
        const uint4* src = (const uint4*)(g_k + base);
        for (int i = tid; i < 8192; i += 512) {
            const int r = i >> 5, u = i & 31;
            *(uint4*)(sKV + r * 512 + ((u ^ (r & 7)) << 4)) = src[i];
        }
    }
    __syncthreads();

    const int sel = lane >> 3, wl = lane & 7;
    const int lr = lane >> 2, lc = lane & 3;
    const uint32_t sQb = su32(sQ), sKVb = su32(sKV);

    // ---- S = Q K^T over this warp's 16 rows x 128 cols ----
    float c[16][4];
    #pragma unroll
    for (int j = 0; j < 16; j++)
        #pragma unroll
        for (int q = 0; q < 4; q++) c[j][q] = 0.f;

    for (int ks = 0; ks < 16; ks++) {
        uint32_t av[4];
        {
            const int r = R0 + wl + ((sel & 1) << 3);
            const int u = 2 * ks + (sel >> 1);
            ldsm4(av, sQb + r * 512 + ((u ^ (r & 7)) << 4));
        }
        #pragma unroll
        for (int np = 0; np < 8; np++) {
            uint32_t bb[4];
            const int rB = nh * 128 + np * 16 + wl + ((sel >> 1) << 3);
            const int uB = 2 * ks + (sel & 1);
            ldsm4(bb, sKVb + rB * 512 + ((uB ^ (rB & 7)) << 4));
            mma16816(c[2 * np],     av, bb);
            mma16816(c[2 * np + 1], av, bb + 2);
        }
    }

    // ---- exp (fixed 2^-8 shift, no max) + pack P + partial row sums ----
    const float KS = 1.4426950408889634f / 16.f;   // log2(e)/16
    float s0 = 0.f, s1 = 0.f;
    uint32_t pa[8][4];
    #pragma unroll
    for (int j = 0; j < 8; j++) {
        const float e00 = ex2f(fmaf(c[2*j][0],   KS, -8.f));
        const float e01 = ex2f(fmaf(c[2*j][1],   KS, -8.f));
        const float e02 = ex2f(fmaf(c[2*j][2],   KS, -8.f));
        const float e03 = ex2f(fmaf(c[2*j][3],   KS, -8.f));
        const float e10 = ex2f(fmaf(c[2*j+1][0], KS, -8.f));
        const float e11 = ex2f(fmaf(c[2*j+1][1], KS, -8.f));
        const float e12 = ex2f(fmaf(c[2*j+1][2], KS, -8.f));
        const float e13 = ex2f(fmaf(c[2*j+1][3], KS, -8.f));
        s0 += e00 + e01 + e10 + e11;
        s1 += e02 + e03 + e12 + e13;
        pa[j][0] = packh2(e00, e01);
        pa[j][1] = packh2(e02, e03);
        pa[j][2] = packh2(e10, e11);
        pa[j][3] = packh2(e12, e13);
    }
    s0 += __shfl_xor_sync(0xffffffffu, s0, 1);
    s0 += __shfl_xor_sync(0xffffffffu, s0, 2);
    s1 += __shfl_xor_sync(0xffffffffu, s1, 1);
    s1 += __shfl_xor_sync(0xffffffffu, s1, 2);
    if (lc == 0) {
        sSum[(R0 + lr) * 2 + nh]     = s0;
        sSum[(R0 + lr + 8) * 2 + nh] = s1;
    }
    __syncthreads();   // K reads done, sums visible

    // fill V (overwrites K region)
    {
        const uint4* src = (const uint4*)(g_v + base);
        for (int i = tid; i < 8192; i += 512) {
            const int r = i >> 5, u = i & 31;
            *(uint4*)(sKV + r * 512 + ((u ^ (r & 7)) << 4)) = src[i];
        }
    }
    const float wad = Wad[0];
    const float f0 = wad / (s0 + sSum[(R0 + lr) * 2 + (nh ^ 1)]);
    const float f1 = wad / (s1 + sSum[(R0 + lr + 8) * 2 + (nh ^ 1)]);
    __syncthreads();   // V ready

    // ---- PV in two column halves; cross-group O exchange via EX ----
    const int h0 = half * 128 + R0 + lr;
    for (int wh = 0; wh < 2; wh++) {
        float o[16][4];
        #pragma unroll
        for (int n = 0; n < 16; n++)
            #pragma unroll
            for (int q = 0; q < 4; q++) o[n][q] = 0.f;

        #pragma unroll
        for (int ks = 0; ks < 8; ks++) {
            #pragma unroll
            for (int nt = 0; nt < 8; nt++) {
                uint32_t bb[4];
                const int rV = nh * 128 + 16 * ks + wl + ((sel & 1) << 3);
                const int uV = wh * 16 + 2 * nt + (sel >> 1);
                ldsm4t(bb, sKVb + rV * 512 + ((uV ^ (rV & 7)) << 4));
                mma16816(o[2 * nt],     pa[ks], bb);
                mma16816(o[2 * nt + 1], pa[ks], bb + 2);
            }
        }
        __syncthreads();

        const bool storer = (wh == 0) ? (nh == 1) : (nh == 0);
        if (storer) {
            #pragma unroll
            for (int j = 0; j < 16; j++) {
                const int colq = j * 8 + 2 * lc;
                *(float2*)(sEX + (R0 + lr) * 130 + colq)     = make_float2(o[j][0], o[j][1]);
                *(float2*)(sEX + (R0 + lr + 8) * 130 + colq) = make_float2(o[j][2], o[j][3]);
            }
        }
        __syncthreads();
        if (!storer) {
            #pragma unroll
            for (int j = 0; j < 16; j++) {
                const int colq = j * 8 + 2 * lc;
                const float2 p0 = *(const float2*)(sEX + (R0 + lr) * 130 + colq);
                const float2 p1 = *(const float2*)(sEX + (R0 + lr + 8) * 130 + colq);
                const size_t i0 = base + (size_t)h0 * 256 + wh * 128 + colq;
                const float2 a0 = *(const float2*)(a + i0);
                float2 r0;
                r0.x = a0.x + f0 * (o[j][0] + p0.x);
                r0.y = a0.y + f0 * (o[j][1] + p0.y);
                *(float2*)(out + i0) = r0;
                const size_t i1 = i0 + 8 * 256;
                const float2 a1 = *(const float2*)(a + i1);
                float2 r1;
                r1.x = a1.x + f1 * (o[j][2] + p1.x);
                r1.y = a1.y + f1 * (o[j][3] + p1.y);
                *(float2*)(out + i1) = r1;
            }
        }
    }
}

// ---------------------------------------------------------------------------
extern "C" void kernel_launch(void* const* d_in, const int* in_sizes, int n_in,
                              void* d_out, int out_size)
{
    const float* a   = (const float*)d_in[0];
    const float* Wq  = (const float*)d_in[1];
    const float* bq  = (const float*)d_in[2];
    const float* Wk  = (const float*)d_in[3];
    const float* bk  = (const float*)d_in[4];
    const float* Wv  = (const float*)d_in[5];
    const float* bv  = (const float*)d_in[6];
    const float* Wad = (const float*)d_in[7];
    float* out = (float*)d_out;

    cudaFuncSetAttribute(qkv_kernel,
                         cudaFuncAttributeMaxDynamicSharedMemorySize, QKV_SMEM_BYTES);
    cudaFuncSetAttribute(attn_kernel,
                         cudaFuncAttributeMaxDynamicSharedMemorySize, ATTN_SMEM_BYTES);

    qkv_kernel<<<16 * 256, 256, QKV_SMEM_BYTES>>>(a, Wq, bq, Wk, bk, Wv, bv);
    attn_kernel<<<2048, 512, ATTN_SMEM_BYTES>>>(a, Wad, out);
}

// round 7
// speedup vs baseline: 7.1444x; 1.2623x over previous
#include <cuda_runtime.h>
#include <cuda_fp16.h>
#include <cstdint>

// ---------------------------------------------------------------------------
// a [B=16, C=64, H=256, W=256] fp32
//   q,k,v = 1x1 conv;  per (b,c): S=QK^T/16, P=softmax(S), O=PV
//   out = a + W_adapt * O
// Round 7: attention restructured for 2 CTAs/SM. CTA = 256 thr, 64 q-rows,
// K split in two 128-row halves (no-max softmax => trivial split-K), P via
// smem tile, O accumulated in registers across halves (no O exchange).
// ---------------------------------------------------------------------------

#define N_ELEM (16 * 64 * 256 * 256)

__device__ __half g_q[N_ELEM];   // [b*64+o][h*256+w]
__device__ __half g_k[N_ELEM];
__device__ __half g_v[N_ELEM];

// ============================ helpers ======================================

__device__ __forceinline__ uint32_t su32(const void* p) {
    return (uint32_t)__cvta_generic_to_shared(p);
}
__device__ __forceinline__ void ldsm4(uint32_t* r, uint32_t addr) {
    asm volatile("ldmatrix.sync.aligned.m8n8.x4.shared.b16 {%0,%1,%2,%3}, [%4];"
        : "=r"(r[0]), "=r"(r[1]), "=r"(r[2]), "=r"(r[3]) : "r"(addr));
}
__device__ __forceinline__ void ldsm4t(uint32_t* r, uint32_t addr) {
    asm volatile("ldmatrix.sync.aligned.m8n8.x4.trans.shared.b16 {%0,%1,%2,%3}, [%4];"
        : "=r"(r[0]), "=r"(r[1]), "=r"(r[2]), "=r"(r[3]) : "r"(addr));
}
__device__ __forceinline__ void mma16816(float* d, const uint32_t* a, const uint32_t* b) {
    asm volatile("mma.sync.aligned.m16n8k16.row.col.f32.f16.f16.f32 "
        "{%0,%1,%2,%3}, {%4,%5,%6,%7}, {%8,%9}, {%0,%1,%2,%3};"
        : "+f"(d[0]), "+f"(d[1]), "+f"(d[2]), "+f"(d[3])
        : "r"(a[0]), "r"(a[1]), "r"(a[2]), "r"(a[3]), "r"(b[0]), "r"(b[1]));
}
__device__ __forceinline__ float ex2f(float x) {
    float y; asm("ex2.approx.f32 %0, %1;" : "=f"(y) : "f"(x)); return y;
}
__device__ __forceinline__ uint32_t packh2(float lo, float hi) {
    __half2 h = __floats2half2_rn(lo, hi);
    return *(uint32_t*)&h;
}

// ======================= Kernel A: QKV (HMMA, C = W * a^T) =================
// (unchanged from R6 — measured ~194us; attn is the target this round)
#define QKV_STG_OFF 58112
#define QKV_SMEM_BYTES (58112 + 32768)

__global__ __launch_bounds__(256, 2) void qkv_kernel(
    const float* __restrict__ a,
    const float* __restrict__ Wq, const float* __restrict__ bq,
    const float* __restrict__ Wk, const float* __restrict__ bk,
    const float* __restrict__ Wv, const float* __restrict__ bv)
{
    extern __shared__ char sm[];
    char* sA = sm;
    char* sW = sm + 32768;
    float* sB = (float*)(sm + 57344);
    char* sStage = sm + QKV_STG_OFF;

    const int tid = threadIdx.x;
    const int b = blockIdx.x >> 8;
    const int P0 = (blockIdx.x & 255) << 8;

    for (int i = tid; i < 6144; i += 256) {
        const int m = i >> 11, j = i & 2047;
        const int o = j >> 5, c2 = j & 31;
        const float* W = (m == 0) ? Wq : ((m == 1) ? Wk : Wv);
        const float f0 = W[o * 64 + 2 * c2];
        const float f1 = W[o * 64 + 2 * c2 + 1];
        const int u = c2 >> 2;
        *(uint32_t*)(sW + m * 8192 + o * 128 + ((u ^ (o & 7)) << 4) + (c2 & 3) * 4)
            = packh2(f0, f1);
    }
    if (tid < 192) {
        const float* bb = (tid < 64) ? bq : ((tid < 128) ? bk : bv);
        sB[tid] = bb[tid & 63];
    }
    {
        const size_t basep = (size_t)b * 64 * 65536 + (size_t)P0 + tid;
        #pragma unroll
        for (int c2 = 0; c2 < 32; c2++) {
            const float f0 = a[basep + (size_t)(2 * c2) * 65536];
            const float f1 = a[basep + (size_t)(2 * c2 + 1) * 65536];
            const int u = c2 >> 2;
            *(uint32_t*)(sA + tid * 128 + ((u ^ (tid & 7)) << 4) + (c2 & 3) * 4)
                = packh2(f0, f1);
        }
    }
    __syncthreads();

    const int wid = tid >> 5, lane = tid & 31;
    const int wp0 = wid * 32;
    const int sel = lane >> 3, wl = lane & 7;
    const int lr = lane >> 2, lc = lane & 3;
    const uint32_t sAb = su32(sA), sWb = su32(sW);

    for (int mat = 0; mat < 3; mat++) {
        float c[4][4][4];
        #pragma unroll
        for (int mt = 0; mt < 4; mt++)
            #pragma unroll
            for (int n = 0; n < 4; n++)
                #pragma unroll
                for (int q = 0; q < 4; q++) c[mt][n][q] = 0.f;

        #pragma unroll
        for (int ng = 0; ng < 2; ng++) {
            uint32_t bfr[4][4];
            #pragma unroll
            for (int ks = 0; ks < 4; ks++) {
                const int rB = wp0 + ng * 16 + wl + ((sel >> 1) << 3);
                const int uB = 2 * ks + (sel & 1);
                ldsm4(bfr[ks], sAb + rB * 128 + ((uB ^ (rB & 7)) << 4));
            }
            #pragma unroll
            for (int mt = 0; mt < 4; mt++) {
                #pragma unroll
                for (int ks = 0; ks < 4; ks++) {
                    uint32_t afr[4];
                    const int rA = mt * 16 + wl + ((sel & 1) << 3);
                    const int uA = 2 * ks + (sel >> 1);
                    ldsm4(afr, sWb + mat * 8192 + rA * 128 + ((uA ^ (rA & 7)) << 4));
                    mma16816(c[mt][2 * ng],     afr, bfr[ks]);
                    mma16816(c[mt][2 * ng + 1], afr, bfr[ks] + 2);
                }
            }
        }

        #pragma unroll
        for (int mt = 0; mt < 4; mt++) {
            const int o0 = mt * 16 + lr, o1 = o0 + 8;
            const float b0 = sB[mat * 64 + o0];
            const float b1 = sB[mat * 64 + o1];
            #pragma unroll
            for (int j = 0; j < 4; j++) {
                const int colp = wp0 + j * 8 + 2 * lc;
                const int pu = colp >> 3, pb = (colp & 7) * 2;
                *(uint32_t*)(sStage + o0 * 512 + ((pu ^ (o0 & 7)) << 4) + pb)
                    = packh2(c[mt][j][0] + b0, c[mt][j][1] + b0);
                *(uint32_t*)(sStage + o1 * 512 + ((pu ^ (o1 & 7)) << 4) + pb)
                    = packh2(c[mt][j][2] + b1, c[mt][j][3] + b1);
            }
        }
        __syncthreads();

        __half* g = (mat == 0) ? g_q : ((mat == 1) ? g_k : g_v);
        #pragma unroll
        for (int oo = 0; oo < 8; oo++) {
            const int o = wid * 8 + oo;
            const uint4 val = *(const uint4*)(sStage + o * 512 + ((lane ^ (o & 7)) << 4));
            *(uint4*)(g + (size_t)(b * 64 + o) * 65536 + P0 + lane * 8) = val;
        }
        __syncthreads();
    }
}

// ======================= Kernel B: attention, 2 CTAs/SM ====================
// grid = 4096 (bc x q-quarter), block = 256 (8 warps).
// Warp = (rg = wid&3 -> 16 rows, cgv = wid>>2 -> S col-half / PV v-half).
// smem: sQ 64x512 @0 (32K); sKV 128x512 @32768 (64K, K then V per kh);
//       sP 64x256 @98304 (16K, fp16 P tile); sSum 64x4 f32 @114688 (1K).
// K split in 2 halves (kh); no-max softmax => O and row-sums just accumulate.
#define AT_Q    0
#define AT_KV   32768
#define AT_P    98304
#define AT_SUM  114688
#define ATTN_SMEM_BYTES 115712

__global__ __launch_bounds__(256, 2) void attn_kernel(
    const float* __restrict__ a,
    const float* __restrict__ Wad,
    float* __restrict__ out)
{
    extern __shared__ char sm[];
    float* sSum = (float*)(sm + AT_SUM);

    const int tid = threadIdx.x, wid = tid >> 5, lane = tid & 31;
    const int rg = wid & 3, cgv = wid >> 2;
    const int R0 = rg * 16;
    const int bc = blockIdx.x >> 2, qq = blockIdx.x & 3;
    const size_t base = (size_t)bc * 65536;

    const int sel = lane >> 3, wl = lane & 7;
    const int lr = lane >> 2, lc = lane & 3;
    const uint32_t sQb = su32(sm + AT_Q), sKVb = su32(sm + AT_KV), sPb = su32(sm + AT_P);

    // ---- Q tile fill (64 rows x 32 units) ----
    {
        const uint4* src = (const uint4*)(g_q + base + (size_t)qq * 16384);
        for (int i = tid; i < 2048; i += 256) {
            const int r = i >> 5, u = i & 31;
            *(uint4*)(sm + AT_Q + r * 512 + ((u ^ (r & 7)) << 4)) = src[i];
        }
    }

    float o[16][4];
    #pragma unroll
    for (int j = 0; j < 16; j++)
        #pragma unroll
        for (int q = 0; q < 4; q++) o[j][q] = 0.f;

    const float KS = 1.4426950408889634f / 16.f;   // log2(e)/16

    for (int kh = 0; kh < 2; kh++) {
        // ---- K fill (128 rows); top sync also covers Q fill / prior V reads
        __syncthreads();
        {
            const uint4* src = (const uint4*)(g_k + base + (size_t)kh * 32768);
            for (int i = tid; i < 4096; i += 256) {
                const int r = i >> 5, u = i & 31;
                *(uint4*)(sm + AT_KV + r * 512 + ((u ^ (r & 7)) << 4)) = src[i];
            }
        }
        __syncthreads();

        // ---- S = Q K^T : warp tile 16 rows x 64 g-cols ----
        float c[8][4];
        #pragma unroll
        for (int j = 0; j < 8; j++)
            #pragma unroll
            for (int q = 0; q < 4; q++) c[j][q] = 0.f;

        for (int ks = 0; ks < 16; ks++) {
            uint32_t av[4];
            {
                const int r = R0 + wl + ((sel & 1) << 3);
                const int u = 2 * ks + (sel >> 1);
                ldsm4(av, sQb + r * 512 + ((u ^ (r & 7)) << 4));
            }
            #pragma unroll
            for (int np = 0; np < 4; np++) {
                uint32_t bb[4];
                const int rB = cgv * 64 + np * 16 + wl + ((sel >> 1) << 3);
                const int uB = 2 * ks + (sel & 1);
                ldsm4(bb, sKVb + rB * 512 + ((uB ^ (rB & 7)) << 4));
                mma16816(c[2 * np],     av, bb);
                mma16816(c[2 * np + 1], av, bb + 2);
            }
        }

        // ---- exp (fixed shift), partial row sums, P -> smem (fp16) ----
        float s0 = 0.f, s1 = 0.f;
        const int r0 = R0 + lr, r1 = R0 + lr + 8;
        #pragma unroll
        for (int j = 0; j < 8; j++) {
            const float e0 = ex2f(fmaf(c[j][0], KS, -8.f));
            const float e1 = ex2f(fmaf(c[j][1], KS, -8.f));
            const float e2 = ex2f(fmaf(c[j][2], KS, -8.f));
            const float e3 = ex2f(fmaf(c[j][3], KS, -8.f));
            s0 += e0 + e1;
            s1 += e2 + e3;
            const int col = cgv * 64 + (j >> 1) * 16 + (j & 1) * 8 + 2 * lc;
            const int u = col >> 3, pb = (col & 7) * 2;
            *(uint32_t*)(sm + AT_P + r0 * 256 + ((u ^ (r0 & 7)) << 4) + pb) = packh2(e0, e1);
            *(uint32_t*)(sm + AT_P + r1 * 256 + ((u ^ (r1 & 7)) << 4) + pb) = packh2(e2, e3);
        }
        s0 += __shfl_xor_sync(0xffffffffu, s0, 1);
        s0 += __shfl_xor_sync(0xffffffffu, s0, 2);
        s1 += __shfl_xor_sync(0xffffffffu, s1, 1);
        s1 += __shfl_xor_sync(0xffffffffu, s1, 2);
        if (lc == 0) {
            sSum[r0 * 4 + kh * 2 + cgv] = s0;
            sSum[r1 * 4 + kh * 2 + cgv] = s1;
        }
        __syncthreads();   // P visible; K reads done

        // ---- V fill (128 rows, same buffer) ----
        {
            const uint4* src = (const uint4*)(g_v + base + (size_t)kh * 32768);
            for (int i = tid; i < 4096; i += 256) {
                const int r = i >> 5, u = i & 31;
                *(uint4*)(sm + AT_KV + r * 512 + ((u ^ (r & 7)) << 4)) = src[i];
            }
        }
        __syncthreads();

        // ---- O += P V : warp tile 16 rows x 128 v-cols (cgv half) ----
        for (int ks = 0; ks < 8; ks++) {
            uint32_t pa[4];
            {
                const int r = R0 + wl + ((sel & 1) << 3);
                const int u = 2 * ks + (sel >> 1);
                ldsm4(pa, sPb + r * 256 + ((u ^ (r & 7)) << 4));
            }
            #pragma unroll
            for (int nt = 0; nt < 8; nt++) {
                uint32_t bb[4];
                const int rV = 16 * ks + wl + ((sel & 1) << 3);
                const int uV = cgv * 16 + 2 * nt + (sel >> 1);
                ldsm4t(bb, sKVb + rV * 512 + ((uV ^ (rV & 7)) << 4));
                mma16816(o[2 * nt],     pa, bb);
                mma16816(o[2 * nt + 1], pa, bb + 2);
            }
        }
    }

    // ---- epilogue: out = a + wad/rowsum * O ----
    const float wad = Wad[0];
    const int r0 = R0 + lr, r1 = R0 + lr + 8;
    const float f0 = wad / (sSum[r0 * 4] + sSum[r0 * 4 + 1] + sSum[r0 * 4 + 2] + sSum[r0 * 4 + 3]);
    const float f1 = wad / (sSum[r1 * 4] + sSum[r1 * 4 + 1] + sSum[r1 * 4 + 2] + sSum[r1 * 4 + 3]);
    const int h0 = qq * 64 + r0;
    #pragma unroll
    for (int j = 0; j < 16; j++) {
        const int col = cgv * 128 + (j >> 1) * 16 + (j & 1) * 8 + 2 * lc;
        const size_t i0 = base + (size_t)h0 * 256 + col;
        const float2 a0 = *(const float2*)(a + i0);
        float2 v0;
        v0.x = a0.x + f0 * o[j][0];
        v0.y = a0.y + f0 * o[j][1];
        *(float2*)(out + i0) = v0;
        const size_t i1 = i0 + 8 * 256;
        const float2 a1 = *(const float2*)(a + i1);
        float2 v1;
        v1.x = a1.x + f1 * o[j][2];
        v1.y = a1.y + f1 * o[j][3];
        *(float2*)(out + i1) = v1;
    }
}

// ---------------------------------------------------------------------------
extern "C" void kernel_launch(void* const* d_in, const int* in_sizes, int n_in,
                              void* d_out, int out_size)
{
    const float* a   = (const float*)d_in[0];
    const float* Wq  = (const float*)d_in[1];
    const float* bq  = (const float*)d_in[2];
    const float* Wk  = (const float*)d_in[3];
    const float* bk  = (const float*)d_in[4];
    const float* Wv  = (const float*)d_in[5];
    const float* bv  = (const float*)d_in[6];
    const float* Wad = (const float*)d_in[7];
    float* out = (float*)d_out;

    cudaFuncSetAttribute(qkv_kernel,
                         cudaFuncAttributeMaxDynamicSharedMemorySize, QKV_SMEM_BYTES);
    cudaFuncSetAttribute(attn_kernel,
                         cudaFuncAttributeMaxDynamicSharedMemorySize, ATTN_SMEM_BYTES);
    cudaFuncSetAttribute(attn_kernel,
                         cudaFuncAttributePreferredSharedMemoryCarveout, 100);

    qkv_kernel<<<16 * 256, 256, QKV_SMEM_BYTES>>>(a, Wq, bq, Wk, bk, Wv, bv);
    attn_kernel<<<4096, 256, ATTN_SMEM_BYTES>>>(a, Wad, out);
}

// round 9
// speedup vs baseline: 8.7431x; 1.2238x over previous
#include <cuda_runtime.h>
#include <cuda_fp16.h>
#include <cstdint>

// ---------------------------------------------------------------------------
// a [B=16, C=64, H=256, W=256] fp32
//   q,k,v = 1x1 conv;  per (b,c): S=QK^T/16, P=softmax(S), O=PV
//   out = a + W_adapt * O
// Round 9: R8 + missing quad-shuffle reduction on the register row-sums
// (the R8 rel_err 3.5e-2 root cause). Squarer warp tiles (S 32x32, PV 32x64),
// cp.async fills (V overlapped with exp), register row-sums.
// ---------------------------------------------------------------------------

#define N_ELEM (16 * 64 * 256 * 256)

__device__ __half g_q[N_ELEM];   // [b*64+o][h*256+w]
__device__ __half g_k[N_ELEM];
__device__ __half g_v[N_ELEM];

// ============================ helpers ======================================

__device__ __forceinline__ uint32_t su32(const void* p) {
    return (uint32_t)__cvta_generic_to_shared(p);
}
__device__ __forceinline__ void ldsm4(uint32_t* r, uint32_t addr) {
    asm volatile("ldmatrix.sync.aligned.m8n8.x4.shared.b16 {%0,%1,%2,%3}, [%4];"
        : "=r"(r[0]), "=r"(r[1]), "=r"(r[2]), "=r"(r[3]) : "r"(addr));
}
__device__ __forceinline__ void ldsm4t(uint32_t* r, uint32_t addr) {
    asm volatile("ldmatrix.sync.aligned.m8n8.x4.trans.shared.b16 {%0,%1,%2,%3}, [%4];"
        : "=r"(r[0]), "=r"(r[1]), "=r"(r[2]), "=r"(r[3]) : "r"(addr));
}
__device__ __forceinline__ void mma16816(float* d, const uint32_t* a, const uint32_t* b) {
    asm volatile("mma.sync.aligned.m16n8k16.row.col.f32.f16.f16.f32 "
        "{%0,%1,%2,%3}, {%4,%5,%6,%7}, {%8,%9}, {%0,%1,%2,%3};"
        : "+f"(d[0]), "+f"(d[1]), "+f"(d[2]), "+f"(d[3])
        : "r"(a[0]), "r"(a[1]), "r"(a[2]), "r"(a[3]), "r"(b[0]), "r"(b[1]));
}
__device__ __forceinline__ float ex2f(float x) {
    float y; asm("ex2.approx.f32 %0, %1;" : "=f"(y) : "f"(x)); return y;
}
__device__ __forceinline__ uint32_t packh2(float lo, float hi) {
    __half2 h = __floats2half2_rn(lo, hi);
    return *(uint32_t*)&h;
}
__device__ __forceinline__ void cp16(uint32_t dst, const void* src) {
    asm volatile("cp.async.cg.shared.global [%0], [%1], 16;"
        :: "r"(dst), "l"(src));
}
#define CP_COMMIT() asm volatile("cp.async.commit_group;" ::: "memory")
#define CP_WAIT0()  asm volatile("cp.async.wait_group 0;" ::: "memory")

// ======================= Kernel A: QKV (HMMA, C = W * a^T) =================
// (unchanged — measured good; attn is the target)
#define QKV_STG_OFF 58112
#define QKV_SMEM_BYTES (58112 + 32768)

__global__ __launch_bounds__(256, 2) void qkv_kernel(
    const float* __restrict__ a,
    const float* __restrict__ Wq, const float* __restrict__ bq,
    const float* __restrict__ Wk, const float* __restrict__ bk,
    const float* __restrict__ Wv, const float* __restrict__ bv)
{
    extern __shared__ char sm[];
    char* sA = sm;
    char* sW = sm + 32768;
    float* sB = (float*)(sm + 57344);
    char* sStage = sm + QKV_STG_OFF;

    const int tid = threadIdx.x;
    const int b = blockIdx.x >> 8;
    const int P0 = (blockIdx.x & 255) << 8;

    for (int i = tid; i < 6144; i += 256) {
        const int m = i >> 11, j = i & 2047;
        const int o = j >> 5, c2 = j & 31;
        const float* W = (m == 0) ? Wq : ((m == 1) ? Wk : Wv);
        const float f0 = W[o * 64 + 2 * c2];
        const float f1 = W[o * 64 + 2 * c2 + 1];
        const int u = c2 >> 2;
        *(uint32_t*)(sW + m * 8192 + o * 128 + ((u ^ (o & 7)) << 4) + (c2 & 3) * 4)
            = packh2(f0, f1);
    }
    if (tid < 192) {
        const float* bb = (tid < 64) ? bq : ((tid < 128) ? bk : bv);
        sB[tid] = bb[tid & 63];
    }
    {
        const size_t basep = (size_t)b * 64 * 65536 + (size_t)P0 + tid;
        #pragma unroll
        for (int c2 = 0; c2 < 32; c2++) {
            const float f0 = a[basep + (size_t)(2 * c2) * 65536];
            const float f1 = a[basep + (size_t)(2 * c2 + 1) * 65536];
            const int u = c2 >> 2;
            *(uint32_t*)(sA + tid * 128 + ((u ^ (tid & 7)) << 4) + (c2 & 3) * 4)
                = packh2(f0, f1);
        }
    }
    __syncthreads();

    const int wid = tid >> 5, lane = tid & 31;
    const int wp0 = wid * 32;
    const int sel = lane >> 3, wl = lane & 7;
    const int lr = lane >> 2, lc = lane & 3;
    const uint32_t sAb = su32(sA), sWb = su32(sW);

    for (int mat = 0; mat < 3; mat++) {
        float c[4][4][4];
        #pragma unroll
        for (int mt = 0; mt < 4; mt++)
            #pragma unroll
            for (int n = 0; n < 4; n++)
                #pragma unroll
                for (int q = 0; q < 4; q++) c[mt][n][q] = 0.f;

        #pragma unroll
        for (int ng = 0; ng < 2; ng++) {
            uint32_t bfr[4][4];
            #pragma unroll
            for (int ks = 0; ks < 4; ks++) {
                const int rB = wp0 + ng * 16 + wl + ((sel >> 1) << 3);
                const int uB = 2 * ks + (sel & 1);
                ldsm4(bfr[ks], sAb + rB * 128 + ((uB ^ (rB & 7)) << 4));
            }
            #pragma unroll
            for (int mt = 0; mt < 4; mt++) {
                #pragma unroll
                for (int ks = 0; ks < 4; ks++) {
                    uint32_t afr[4];
                    const int rA = mt * 16 + wl + ((sel & 1) << 3);
                    const int uA = 2 * ks + (sel >> 1);
                    ldsm4(afr, sWb + mat * 8192 + rA * 128 + ((uA ^ (rA & 7)) << 4));
                    mma16816(c[mt][2 * ng],     afr, bfr[ks]);
                    mma16816(c[mt][2 * ng + 1], afr, bfr[ks] + 2);
                }
            }
        }

        #pragma unroll
        for (int mt = 0; mt < 4; mt++) {
            const int o0 = mt * 16 + lr, o1 = o0 + 8;
            const float b0 = sB[mat * 64 + o0];
            const float b1 = sB[mat * 64 + o1];
            #pragma unroll
            for (int j = 0; j < 4; j++) {
                const int colp = wp0 + j * 8 + 2 * lc;
                const int pu = colp >> 3, pb = (colp & 7) * 2;
                *(uint32_t*)(sStage + o0 * 512 + ((pu ^ (o0 & 7)) << 4) + pb)
                    = packh2(c[mt][j][0] + b0, c[mt][j][1] + b0);
                *(uint32_t*)(sStage + o1 * 512 + ((pu ^ (o1 & 7)) << 4) + pb)
                    = packh2(c[mt][j][2] + b1, c[mt][j][3] + b1);
            }
        }
        __syncthreads();

        __half* g = (mat == 0) ? g_q : ((mat == 1) ? g_k : g_v);
        #pragma unroll
        for (int oo = 0; oo < 8; oo++) {
            const int o = wid * 8 + oo;
            const uint4 val = *(const uint4*)(sStage + o * 512 + ((lane ^ (o & 7)) << 4));
            *(uint4*)(g + (size_t)(b * 64 + o) * 65536 + P0 + lane * 8) = val;
        }
        __syncthreads();
    }
}

// ======================= Kernel B: attention ===============================
// grid = 4096 (bc x q-quarter), block = 256 (8 warps), 2 CTAs/SM.
// S-phase warp tile 32x32 (rg=wid&1, cg=wid>>1); PV warp tile 32x64.
// P via smem (64x128 fp16/kh). Row sums in regs (quad-reduced at the end).
// smem: sQ 64x512 @0 (32K); sKV 128x512 @32768 (64K); sP @98304 (16K);
//       sSum 64x4 f32 @114688 (1K). Total 115712 B.
#define AT_Q    0
#define AT_KV   32768
#define AT_P    98304
#define AT_SUM  114688
#define ATTN_SMEM_BYTES 115712

__global__ __launch_bounds__(256, 2) void attn_kernel(
    const float* __restrict__ a,
    const float* __restrict__ Wad,
    float* __restrict__ out)
{
    extern __shared__ char sm[];
    float* sSum = (float*)(sm + AT_SUM);

    const int tid = threadIdx.x, wid = tid >> 5, lane = tid & 31;
    const int rg = wid & 1, cg = wid >> 1;        // cg doubles as vg in PV
    const int R0 = rg * 32;
    const int C0 = cg * 32;                        // S col base (within kh)
    const int V0 = cg * 64;                        // PV v-col base
    const int bc = blockIdx.x >> 2, qq = blockIdx.x & 3;
    const size_t base = (size_t)bc * 65536;

    const int sel = lane >> 3, wl = lane & 7;
    const int lr = lane >> 2, lc = lane & 3;
    const uint32_t sQb = su32(sm + AT_Q), sKVb = su32(sm + AT_KV), sPb = su32(sm + AT_P);

    // ---- async fills: Q (64 rows) + K half 0 (128 rows) ----
    {
        const __half* src = g_q + base + (size_t)qq * 16384;
        #pragma unroll
        for (int t = 0; t < 8; t++) {
            const int i = t * 256 + tid;
            const int r = i >> 5, u = i & 31;
            cp16(sQb + r * 512 + ((u ^ (r & 7)) << 4), src + i * 8);
        }
    }
    {
        const __half* src = g_k + base;
        #pragma unroll
        for (int t = 0; t < 16; t++) {
            const int i = t * 256 + tid;
            const int r = i >> 5, u = i & 31;
            cp16(sKVb + r * 512 + ((u ^ (r & 7)) << 4), src + i * 8);
        }
    }
    CP_COMMIT();

    float o[2][8][4];
    #pragma unroll
    for (int mi = 0; mi < 2; mi++)
        #pragma unroll
        for (int n = 0; n < 8; n++)
            #pragma unroll
            for (int q = 0; q < 4; q++) o[mi][n][q] = 0.f;

    float sacc[2][2] = {{0.f, 0.f}, {0.f, 0.f}};   // [mi][row/row+8]
    const float KS = 1.4426950408889634f / 16.f;   // log2(e)/16

    CP_WAIT0();
    __syncthreads();

    for (int kh = 0; kh < 2; kh++) {
        // ---- S = Q K^T : warp tile 32 rows x 32 g-cols ----
        float c[2][4][4];
        #pragma unroll
        for (int mi = 0; mi < 2; mi++)
            #pragma unroll
            for (int n = 0; n < 4; n++)
                #pragma unroll
                for (int q = 0; q < 4; q++) c[mi][n][q] = 0.f;

        for (int ks = 0; ks < 16; ks++) {
            uint32_t a0[4], a1[4];
            {
                const int r = R0 + wl + ((sel & 1) << 3);
                const int u = 2 * ks + (sel >> 1);
                ldsm4(a0, sQb + r * 512 + ((u ^ (r & 7)) << 4));
                const int r2 = r + 16;
                ldsm4(a1, sQb + r2 * 512 + ((u ^ (r2 & 7)) << 4));
            }
            #pragma unroll
            for (int nb = 0; nb < 2; nb++) {
                uint32_t bb[4];
                const int rB = C0 + nb * 16 + wl + ((sel >> 1) << 3);
                const int uB = 2 * ks + (sel & 1);
                ldsm4(bb, sKVb + rB * 512 + ((uB ^ (rB & 7)) << 4));
                mma16816(c[0][2 * nb],     a0, bb);
                mma16816(c[0][2 * nb + 1], a0, bb + 2);
                mma16816(c[1][2 * nb],     a1, bb);
                mma16816(c[1][2 * nb + 1], a1, bb + 2);
            }
        }
        __syncthreads();   // all K reads done -> buffer reusable

        // ---- issue V fill (overlaps exp/P-write below) ----
        {
            const __half* src = g_v + base + (size_t)kh * 32768;
            #pragma unroll
            for (int t = 0; t < 16; t++) {
                const int i = t * 256 + tid;
                const int r = i >> 5, u = i & 31;
                cp16(sKVb + r * 512 + ((u ^ (r & 7)) << 4), src + i * 8);
            }
        }
        CP_COMMIT();

        // ---- exp (fixed 2^-8 shift), P -> smem fp16, sums in regs ----
        #pragma unroll
        for (int mi = 0; mi < 2; mi++) {
            const int rb = R0 + 16 * mi + lr, rb8 = rb + 8;
            #pragma unroll
            for (int ni = 0; ni < 4; ni++) {
                const float e0 = ex2f(fmaf(c[mi][ni][0], KS, -8.f));
                const float e1 = ex2f(fmaf(c[mi][ni][1], KS, -8.f));
                const float e2 = ex2f(fmaf(c[mi][ni][2], KS, -8.f));
                const float e3 = ex2f(fmaf(c[mi][ni][3], KS, -8.f));
                sacc[mi][0] += e0 + e1;
                sacc[mi][1] += e2 + e3;
                const int u = (C0 >> 3) + ni;
                *(uint32_t*)(sm + AT_P + rb * 256 + ((u ^ (rb & 7)) << 4) + 4 * lc)
                    = packh2(e0, e1);
                *(uint32_t*)(sm + AT_P + rb8 * 256 + ((u ^ (rb8 & 7)) << 4) + 4 * lc)
                    = packh2(e2, e3);
            }
        }
        CP_WAIT0();
        __syncthreads();   // V ready, P visible

        // ---- O += P V : warp tile 32 rows x 64 v-cols ----
        for (int ks = 0; ks < 8; ks++) {
            uint32_t p0[4], p1[4];
            {
                const int r = R0 + wl + ((sel & 1) << 3);
                const int u = 2 * ks + (sel >> 1);
                ldsm4(p0, sPb + r * 256 + ((u ^ (r & 7)) << 4));
                const int r2 = r + 16;
                ldsm4(p1, sPb + r2 * 256 + ((u ^ (r2 & 7)) << 4));
            }
            #pragma unroll
            for (int nt = 0; nt < 4; nt++) {
                uint32_t bb[4];
                const int rV = 16 * ks + wl + ((sel & 1) << 3);
                const int uV = cg * 8 + 2 * nt + (sel >> 1);
                ldsm4t(bb, sKVb + rV * 512 + ((uV ^ (rV & 7)) << 4));
                mma16816(o[0][2 * nt],     p0, bb);
                mma16816(o[0][2 * nt + 1], p0, bb + 2);
                mma16816(o[1][2 * nt],     p1, bb);
                mma16816(o[1][2 * nt + 1], p1, bb + 2);
            }
        }
        __syncthreads();   // V + P reads done

        // ---- fill K half 1 for next iteration ----
        if (kh == 0) {
            const __half* src = g_k + base + 32768;
            #pragma unroll
            for (int t = 0; t < 16; t++) {
                const int i = t * 256 + tid;
                const int r = i >> 5, u = i & 31;
                cp16(sKVb + r * 512 + ((u ^ (r & 7)) << 4), src + i * 8);
            }
            CP_COMMIT();
            CP_WAIT0();
            __syncthreads();
        }
    }

    // ---- quad reduction (lanes differ only in lc): full row sums ----
    #pragma unroll
    for (int mi = 0; mi < 2; mi++) {
        #pragma unroll
        for (int hh = 0; hh < 2; hh++) {
            sacc[mi][hh] += __shfl_xor_sync(0xffffffffu, sacc[mi][hh], 1);
            sacc[mi][hh] += __shfl_xor_sync(0xffffffffu, sacc[mi][hh], 2);
        }
    }

    // ---- publish row sums (per warp: rows R0..R0+31, col-group cg) ----
    if (lc == 0) {
        #pragma unroll
        for (int mi = 0; mi < 2; mi++) {
            sSum[(R0 + 16 * mi + lr) * 4 + cg]     = sacc[mi][0];
            sSum[(R0 + 16 * mi + lr + 8) * 4 + cg] = sacc[mi][1];
        }
    }
    __syncthreads();

    // ---- epilogue: out = a + wad/rowsum * O ----
    const float wad = Wad[0];
    #pragma unroll
    for (int mi = 0; mi < 2; mi++) {
        const int rb = R0 + 16 * mi + lr;
        const float f0 = wad / (sSum[rb * 4] + sSum[rb * 4 + 1]
                              + sSum[rb * 4 + 2] + sSum[rb * 4 + 3]);
        const float f1 = wad / (sSum[(rb + 8) * 4] + sSum[(rb + 8) * 4 + 1]
                              + sSum[(rb + 8) * 4 + 2] + sSum[(rb + 8) * 4 + 3]);
        const int h0 = qq * 64 + rb;
        #pragma unroll
        for (int ni = 0; ni < 8; ni++) {
            const int col = V0 + ni * 8 + 2 * lc;
            const size_t i0 = base + (size_t)h0 * 256 + col;
            const float2 a0 = *(const float2*)(a + i0);
            float2 v0;
            v0.x = a0.x + f0 * o[mi][ni][0];
            v0.y = a0.y + f0 * o[mi][ni][1];
            *(float2*)(out + i0) = v0;
            const size_t i1 = i0 + 8 * 256;
            const float2 a1 = *(const float2*)(a + i1);
            float2 v1;
            v1.x = a1.x + f1 * o[mi][ni][2];
            v1.y = a1.y + f1 * o[mi][ni][3];
            *(float2*)(out + i1) = v1;
        }
    }
}

// ---------------------------------------------------------------------------
extern "C" void kernel_launch(void* const* d_in, const int* in_sizes, int n_in,
                              void* d_out, int out_size)
{
    const float* a   = (const float*)d_in[0];
    const float* Wq  = (const float*)d_in[1];
    const float* bq  = (const float*)d_in[2];
    const float* Wk  = (const float*)d_in[3];
    const float* bk  = (const float*)d_in[4];
    const float* Wv  = (const float*)d_in[5];
    const float* bv  = (const float*)d_in[6];
    const float* Wad = (const float*)d_in[7];
    float* out = (float*)d_out;

    cudaFuncSetAttribute(qkv_kernel,
                         cudaFuncAttributeMaxDynamicSharedMemorySize, QKV_SMEM_BYTES);
    cudaFuncSetAttribute(attn_kernel,
                         cudaFuncAttributeMaxDynamicSharedMemorySize, ATTN_SMEM_BYTES);
    cudaFuncSetAttribute(attn_kernel,
                         cudaFuncAttributePreferredSharedMemoryCarveout, 100);

    qkv_kernel<<<16 * 256, 256, QKV_SMEM_BYTES>>>(a, Wq, bq, Wk, bk, Wv, bv);
    attn_kernel<<<4096, 256, ATTN_SMEM_BYTES>>>(a, Wad, out);
}

// round 10
// speedup vs baseline: 9.7760x; 1.1181x over previous
#include <cuda_runtime.h>
#include <cuda_fp16.h>
#include <cstdint>

// ---------------------------------------------------------------------------
// a [B=16, C=64, H=256, W=256] fp32
//   q,k,v = 1x1 conv;  per (b,c): S=QK^T/16, P=softmax(S), O=PV
//   out = a + W_adapt * O
// Round 10: phase-reordered attention. S for both K halves first (P tiles in
// smem; P1 overlays dead Q), then PV with V streamed via a 2x32KB ring.
// Register peaks split (c and o never co-live) -> ptxas slack for pipelining;
// every cp.async fill overlapped with compute.
// ---------------------------------------------------------------------------

#define N_ELEM (16 * 64 * 256 * 256)

__device__ __half g_q[N_ELEM];   // [b*64+o][h*256+w]
__device__ __half g_k[N_ELEM];
__device__ __half g_v[N_ELEM];

// ============================ helpers ======================================

__device__ __forceinline__ uint32_t su32(const void* p) {
    return (uint32_t)__cvta_generic_to_shared(p);
}
__device__ __forceinline__ void ldsm4(uint32_t* r, uint32_t addr) {
    asm volatile("ldmatrix.sync.aligned.m8n8.x4.shared.b16 {%0,%1,%2,%3}, [%4];"
        : "=r"(r[0]), "=r"(r[1]), "=r"(r[2]), "=r"(r[3]) : "r"(addr));
}
__device__ __forceinline__ void ldsm4t(uint32_t* r, uint32_t addr) {
    asm volatile("ldmatrix.sync.aligned.m8n8.x4.trans.shared.b16 {%0,%1,%2,%3}, [%4];"
        : "=r"(r[0]), "=r"(r[1]), "=r"(r[2]), "=r"(r[3]) : "r"(addr));
}
__device__ __forceinline__ void mma16816(float* d, const uint32_t* a, const uint32_t* b) {
    asm volatile("mma.sync.aligned.m16n8k16.row.col.f32.f16.f16.f32 "
        "{%0,%1,%2,%3}, {%4,%5,%6,%7}, {%8,%9}, {%0,%1,%2,%3};"
        : "+f"(d[0]), "+f"(d[1]), "+f"(d[2]), "+f"(d[3])
        : "r"(a[0]), "r"(a[1]), "r"(a[2]), "r"(a[3]), "r"(b[0]), "r"(b[1]));
}
__device__ __forceinline__ float ex2f(float x) {
    float y; asm("ex2.approx.f32 %0, %1;" : "=f"(y) : "f"(x)); return y;
}
__device__ __forceinline__ uint32_t packh2(float lo, float hi) {
    __half2 h = __floats2half2_rn(lo, hi);
    return *(uint32_t*)&h;
}
__device__ __forceinline__ void cp16(uint32_t dst, const void* src) {
    asm volatile("cp.async.cg.shared.global [%0], [%1], 16;"
        :: "r"(dst), "l"(src));
}
#define CP_COMMIT() asm volatile("cp.async.commit_group;" ::: "memory")
#define CP_WAIT0()  asm volatile("cp.async.wait_group 0;" ::: "memory")

// ======================= Kernel A: QKV (HMMA, C = W * a^T) =================
// (unchanged from R9 — attn is the A/B target)
#define QKV_STG_OFF 58112
#define QKV_SMEM_BYTES (58112 + 32768)

__global__ __launch_bounds__(256, 2) void qkv_kernel(
    const float* __restrict__ a,
    const float* __restrict__ Wq, const float* __restrict__ bq,
    const float* __restrict__ Wk, const float* __restrict__ bk,
    const float* __restrict__ Wv, const float* __restrict__ bv)
{
    extern __shared__ char sm[];
    char* sA = sm;
    char* sW = sm + 32768;
    float* sB = (float*)(sm + 57344);
    char* sStage = sm + QKV_STG_OFF;

    const int tid = threadIdx.x;
    const int b = blockIdx.x >> 8;
    const int P0 = (blockIdx.x & 255) << 8;

    for (int i = tid; i < 6144; i += 256) {
        const int m = i >> 11, j = i & 2047;
        const int o = j >> 5, c2 = j & 31;
        const float* W = (m == 0) ? Wq : ((m == 1) ? Wk : Wv);
        const float f0 = W[o * 64 + 2 * c2];
        const float f1 = W[o * 64 + 2 * c2 + 1];
        const int u = c2 >> 2;
        *(uint32_t*)(sW + m * 8192 + o * 128 + ((u ^ (o & 7)) << 4) + (c2 & 3) * 4)
            = packh2(f0, f1);
    }
    if (tid < 192) {
        const float* bb = (tid < 64) ? bq : ((tid < 128) ? bk : bv);
        sB[tid] = bb[tid & 63];
    }
    {
        const size_t basep = (size_t)b * 64 * 65536 + (size_t)P0 + tid;
        #pragma unroll
        for (int c2 = 0; c2 < 32; c2++) {
            const float f0 = a[basep + (size_t)(2 * c2) * 65536];
            const float f1 = a[basep + (size_t)(2 * c2 + 1) * 65536];
            const int u = c2 >> 2;
            *(uint32_t*)(sA + tid * 128 + ((u ^ (tid & 7)) << 4) + (c2 & 3) * 4)
                = packh2(f0, f1);
        }
    }
    __syncthreads();

    const int wid = tid >> 5, lane = tid & 31;
    const int wp0 = wid * 32;
    const int sel = lane >> 3, wl = lane & 7;
    const int lr = lane >> 2, lc = lane & 3;
    const uint32_t sAb = su32(sA), sWb = su32(sW);

    for (int mat = 0; mat < 3; mat++) {
        float c[4][4][4];
        #pragma unroll
        for (int mt = 0; mt < 4; mt++)
            #pragma unroll
            for (int n = 0; n < 4; n++)
                #pragma unroll
                for (int q = 0; q < 4; q++) c[mt][n][q] = 0.f;

        #pragma unroll
        for (int ng = 0; ng < 2; ng++) {
            uint32_t bfr[4][4];
            #pragma unroll
            for (int ks = 0; ks < 4; ks++) {
                const int rB = wp0 + ng * 16 + wl + ((sel >> 1) << 3);
                const int uB = 2 * ks + (sel & 1);
                ldsm4(bfr[ks], sAb + rB * 128 + ((uB ^ (rB & 7)) << 4));
            }
            #pragma unroll
            for (int mt = 0; mt < 4; mt++) {
                #pragma unroll
                for (int ks = 0; ks < 4; ks++) {
                    uint32_t afr[4];
                    const int rA = mt * 16 + wl + ((sel & 1) << 3);
                    const int uA = 2 * ks + (sel >> 1);
                    ldsm4(afr, sWb + mat * 8192 + rA * 128 + ((uA ^ (rA & 7)) << 4));
                    mma16816(c[mt][2 * ng],     afr, bfr[ks]);
                    mma16816(c[mt][2 * ng + 1], afr, bfr[ks] + 2);
                }
            }
        }

        #pragma unroll
        for (int mt = 0; mt < 4; mt++) {
            const int o0 = mt * 16 + lr, o1 = o0 + 8;
            const float b0 = sB[mat * 64 + o0];
            const float b1 = sB[mat * 64 + o1];
            #pragma unroll
            for (int j = 0; j < 4; j++) {
                const int colp = wp0 + j * 8 + 2 * lc;
                const int pu = colp >> 3, pb = (colp & 7) * 2;
                *(uint32_t*)(sStage + o0 * 512 + ((pu ^ (o0 & 7)) << 4) + pb)
                    = packh2(c[mt][j][0] + b0, c[mt][j][1] + b0);
                *(uint32_t*)(sStage + o1 * 512 + ((pu ^ (o1 & 7)) << 4) + pb)
                    = packh2(c[mt][j][2] + b1, c[mt][j][3] + b1);
            }
        }
        __syncthreads();

        __half* g = (mat == 0) ? g_q : ((mat == 1) ? g_k : g_v);
        #pragma unroll
        for (int oo = 0; oo < 8; oo++) {
            const int o = wid * 8 + oo;
            const uint4 val = *(const uint4*)(sStage + o * 512 + ((lane ^ (o & 7)) << 4));
            *(uint4*)(g + (size_t)(b * 64 + o) * 65536 + P0 + lane * 8) = val;
        }
        __syncthreads();
    }
}

// ======================= Kernel B: attention ===============================
// grid = 4096 (bc x q-quarter), block = 256 (8 warps), 2 CTAs/SM.
// Phases: S(kh0) -> exp->P0 (K1 fill overlapped) -> S(kh1) -> exp->P1
// (V-chunk0 fill overlapped; P1 overlays dead Q) -> 4x PV chunks with V
// streamed through a 2x32KB ring (fills overlapped with PV compute).
// smem: sQ/P1 @0 (32K); K / V-ring @32768 (64K); P0 @98304 (16K);
//       sSum 64x4 f32 @114688 (1K). Total 115712 B.
#define AT_Q    0
#define AT_K    32768
#define AT_P0   98304
#define AT_SUM  114688
#define ATTN_SMEM_BYTES 115712

__global__ __launch_bounds__(256, 2) void attn_kernel(
    const float* __restrict__ a,
    const float* __restrict__ Wad,
    float* __restrict__ out)
{
    extern __shared__ char sm[];
    float* sSum = (float*)(sm + AT_SUM);

    const int tid = threadIdx.x, wid = tid >> 5, lane = tid & 31;
    const int rg = wid & 1, cg = wid >> 1;        // cg doubles as vg in PV
    const int R0 = rg * 32;
    const int C0 = cg * 32;                        // S col base (within kh)
    const int V0 = cg * 64;                        // PV v-col base
    const int bc = blockIdx.x >> 2, qq = blockIdx.x & 3;
    const size_t base = (size_t)bc * 65536;

    const int sel = lane >> 3, wl = lane & 7;
    const int lr = lane >> 2, lc = lane & 3;
    const uint32_t sQb = su32(sm + AT_Q), sKb = su32(sm + AT_K), sP0b = su32(sm + AT_P0);

    // ---- async fills: Q (64 rows) + K half 0 (128 rows) ----
    {
        const __half* src = g_q + base + (size_t)qq * 16384;
        #pragma unroll
        for (int t = 0; t < 8; t++) {
            const int i = t * 256 + tid;
            const int r = i >> 5, u = i & 31;
            cp16(sQb + r * 512 + ((u ^ (r & 7)) << 4), src + i * 8);
        }
    }
    {
        const __half* src = g_k + base;
        #pragma unroll
        for (int t = 0; t < 16; t++) {
            const int i = t * 256 + tid;
            const int r = i >> 5, u = i & 31;
            cp16(sKb + r * 512 + ((u ^ (r & 7)) << 4), src + i * 8);
        }
    }
    CP_COMMIT();

    float sacc[2][2] = {{0.f, 0.f}, {0.f, 0.f}};   // [mi][row/row+8]
    const float KS = 1.4426950408889634f / 16.f;   // log2(e)/16

    CP_WAIT0();
    __syncthreads();

    // ================= S phases (both K halves), c regs only ===============
    for (int kh = 0; kh < 2; kh++) {
        float c[2][4][4];
        #pragma unroll
        for (int mi = 0; mi < 2; mi++)
            #pragma unroll
            for (int n = 0; n < 4; n++)
                #pragma unroll
                for (int q = 0; q < 4; q++) c[mi][n][q] = 0.f;

        for (int ks = 0; ks < 16; ks++) {
            uint32_t a0[4], a1[4];
            {
                const int r = R0 + wl + ((sel & 1) << 3);
                const int u = 2 * ks + (sel >> 1);
                ldsm4(a0, sQb + r * 512 + ((u ^ (r & 7)) << 4));
                const int r2 = r + 16;
                ldsm4(a1, sQb + r2 * 512 + ((u ^ (r2 & 7)) << 4));
            }
            #pragma unroll
            for (int nb = 0; nb < 2; nb++) {
                uint32_t bb[4];
                const int rB = C0 + nb * 16 + wl + ((sel >> 1) << 3);
                const int uB = 2 * ks + (sel & 1);
                ldsm4(bb, sKb + rB * 512 + ((uB ^ (rB & 7)) << 4));
                mma16816(c[0][2 * nb],     a0, bb);
                mma16816(c[0][2 * nb + 1], a0, bb + 2);
                mma16816(c[1][2 * nb],     a1, bb);
                mma16816(c[1][2 * nb + 1], a1, bb + 2);
            }
        }
        __syncthreads();   // K half (and Q, when kh=1) reads done

        // overlap the next fill with the exp phase below
        if (kh == 0) {
            const __half* src = g_k + base + 32768;   // K half 1
            #pragma unroll
            for (int t = 0; t < 16; t++) {
                const int i = t * 256 + tid;
                const int r = i >> 5, u = i & 31;
                cp16(sKb + r * 512 + ((u ^ (r & 7)) << 4), src + i * 8);
            }
        } else {
            const __half* src = g_v + base;           // V chunk 0 -> ring buf 0
            #pragma unroll
            for (int t = 0; t < 8; t++) {
                const int i = t * 256 + tid;
                const int r = i >> 5, u = i & 31;
                cp16(sKb + r * 512 + ((u ^ (r & 7)) << 4), src + i * 8);
            }
        }
        CP_COMMIT();

        // exp (fixed 2^-8 shift) -> P tile (kh0: P0 region; kh1: dead Q region)
        const uint32_t pBase = (kh == 0) ? (uint32_t)AT_P0 : (uint32_t)AT_Q;
        #pragma unroll
        for (int mi = 0; mi < 2; mi++) {
            const int rb = R0 + 16 * mi + lr, rb8 = rb + 8;
            #pragma unroll
            for (int ni = 0; ni < 4; ni++) {
                const float e0 = ex2f(fmaf(c[mi][ni][0], KS, -8.f));
                const float e1 = ex2f(fmaf(c[mi][ni][1], KS, -8.f));
                const float e2 = ex2f(fmaf(c[mi][ni][2], KS, -8.f));
                const float e3 = ex2f(fmaf(c[mi][ni][3], KS, -8.f));
                sacc[mi][0] += e0 + e1;
                sacc[mi][1] += e2 + e3;
                const int u = (C0 >> 3) + ni;
                *(uint32_t*)(sm + pBase + rb * 256 + ((u ^ (rb & 7)) << 4) + 4 * lc)
                    = packh2(e0, e1);
                *(uint32_t*)(sm + pBase + rb8 * 256 + ((u ^ (rb8 & 7)) << 4) + 4 * lc)
                    = packh2(e2, e3);
            }
        }
        CP_WAIT0();
        __syncthreads();   // next tile ready; P visible
    }

    // ================= PV: 4 chunks of 64 V-rows, 2x32KB ring ==============
    float o[2][8][4];
    #pragma unroll
    for (int mi = 0; mi < 2; mi++)
        #pragma unroll
        for (int n = 0; n < 8; n++)
            #pragma unroll
            for (int q = 0; q < 4; q++) o[mi][n][q] = 0.f;

    for (int ch = 0; ch < 4; ch++) {
        // prefetch next V chunk into the other ring buffer (overlaps PV below)
        if (ch < 3) {
            const __half* src = g_v + base + (size_t)(ch + 1) * 16384;
            const uint32_t dst = sKb + (uint32_t)(((ch + 1) & 1) * 32768);
            #pragma unroll
            for (int t = 0; t < 8; t++) {
                const int i = t * 256 + tid;
                const int r = i >> 5, u = i & 31;
                cp16(dst + r * 512 + ((u ^ (r & 7)) << 4), src + i * 8);
            }
            CP_COMMIT();
        }

        const uint32_t vbuf = sKb + (uint32_t)((ch & 1) * 32768);
        const uint32_t pb = (ch < 2) ? sP0b : sQb;
        const int ko = (ch & 1) * 4;            // k-step offset within P tile

        for (int ks = 0; ks < 4; ks++) {
            uint32_t p0[4], p1[4];
            {
                const int r = R0 + wl + ((sel & 1) << 3);
                const int u = 2 * (ko + ks) + (sel >> 1);
                ldsm4(p0, pb + r * 256 + ((u ^ (r & 7)) << 4));
                const int r2 = r + 16;
                ldsm4(p1, pb + r2 * 256 + ((u ^ (r2 & 7)) << 4));
            }
            #pragma unroll
            for (int nt = 0; nt < 4; nt++) {
                uint32_t bb[4];
                const int rV = 16 * ks + wl + ((sel & 1) << 3);
                const int uV = cg * 8 + 2 * nt + (sel >> 1);
                ldsm4t(bb, vbuf + rV * 512 + ((uV ^ (rV & 7)) << 4));
                mma16816(o[0][2 * nt],     p0, bb);
                mma16816(o[0][2 * nt + 1], p0, bb + 2);
                mma16816(o[1][2 * nt],     p1, bb);
                mma16816(o[1][2 * nt + 1], p1, bb + 2);
            }
        }

        if (ch < 3) {
            CP_WAIT0();
            __syncthreads();   // next chunk ready; this buffer released
        }
    }

    // ---- quad reduction (lanes differ only in lc): full row sums ----
    #pragma unroll
    for (int mi = 0; mi < 2; mi++) {
        #pragma unroll
        for (int hh = 0; hh < 2; hh++) {
            sacc[mi][hh] += __shfl_xor_sync(0xffffffffu, sacc[mi][hh], 1);
            sacc[mi][hh] += __shfl_xor_sync(0xffffffffu, sacc[mi][hh], 2);
        }
    }
    if (lc == 0) {
        #pragma unroll
        for (int mi = 0; mi < 2; mi++) {
            sSum[(R0 + 16 * mi + lr) * 4 + cg]     = sacc[mi][0];
            sSum[(R0 + 16 * mi + lr + 8) * 4 + cg] = sacc[mi][1];
        }
    }
    __syncthreads();

    // ---- epilogue: out = a + wad/rowsum * O ----
    const float wad = Wad[0];
    #pragma unroll
    for (int mi = 0; mi < 2; mi++) {
        const int rb = R0 + 16 * mi + lr;
        const float f0 = wad / (sSum[rb * 4] + sSum[rb * 4 + 1]
                              + sSum[rb * 4 + 2] + sSum[rb * 4 + 3]);
        const float f1 = wad / (sSum[(rb + 8) * 4] + sSum[(rb + 8) * 4 + 1]
                              + sSum[(rb + 8) * 4 + 2] + sSum[(rb + 8) * 4 + 3]);
        const int h0 = qq * 64 + rb;
        #pragma unroll
        for (int ni = 0; ni < 8; ni++) {
            const int col = V0 + ni * 8 + 2 * lc;
            const size_t i0 = base + (size_t)h0 * 256 + col;
            const float2 a0 = *(const float2*)(a + i0);
            float2 v0;
            v0.x = a0.x + f0 * o[mi][ni][0];
            v0.y = a0.y + f0 * o[mi][ni][1];
            *(float2*)(out + i0) = v0;
            const size_t i1 = i0 + 8 * 256;
            const float2 a1 = *(const float2*)(a + i1);
            float2 v1;
            v1.x = a1.x + f1 * o[mi][ni][2];
            v1.y = a1.y + f1 * o[mi][ni][3];
            *(float2*)(out + i1) = v1;
        }
    }
}

// ---------------------------------------------------------------------------
extern "C" void kernel_launch(void* const* d_in, const int* in_sizes, int n_in,
                              void* d_out, int out_size)
{
    const float* a   = (const float*)d_in[0];
    const float* Wq  = (const float*)d_in[1];
    const float* bq  = (const float*)d_in[2];
    const float* Wk  = (const float*)d_in[3];
    const float* bk  = (const float*)d_in[4];
    const float* Wv  = (const float*)d_in[5];
    const float* bv  = (const float*)d_in[6];
    const float* Wad = (const float*)d_in[7];
    float* out = (float*)d_out;

    cudaFuncSetAttribute(qkv_kernel,
                         cudaFuncAttributeMaxDynamicSharedMemorySize, QKV_SMEM_BYTES);
    cudaFuncSetAttribute(attn_kernel,
                         cudaFuncAttributeMaxDynamicSharedMemorySize, ATTN_SMEM_BYTES);
    cudaFuncSetAttribute(attn_kernel,
                         cudaFuncAttributePreferredSharedMemoryCarveout, 100);

    qkv_kernel<<<16 * 256, 256, QKV_SMEM_BYTES>>>(a, Wq, bq, Wk, bk, Wv, bv);
    attn_kernel<<<4096, 256, ATTN_SMEM_BYTES>>>(a, Wad, out);
}